// round 7
// baseline (speedup 1.0000x reference)
#include <cuda_runtime.h>
#include <cuda_bf16.h>
#include <cstdint>
#include <cstring>

// Problem constants (fixed by dataset; runtime values read from in_sizes).
#define NMAX 50000
#define EMAX 600000

// ---------------- scratch (device globals; no allocation allowed) ----------
// All mutable state is rebuilt every launch; counters/flags are returned to
// zero at the end of each launch -> deterministic across graph replays.
__device__ int   g_cnt[NMAX];
__device__ int   g_rowptr[NMAX + 1];
__device__ int   g_wptr[NMAX];
__device__ int   g_esrc[EMAX];
__device__ float g_dinv[NMAX];
__device__ float g_H[(size_t)NMAX * 128];
__device__ float g_A[(size_t)NMAX * 128];
__device__ volatile int g_btot[64];   // scan block totals (+1 = published); reset in-kernel
__device__ int   g_bdone;             // scan completion counter; reset in-kernel

// ---------------- f32x2 packed FMA (ptxas never auto-fuses this) -----------
__device__ __forceinline__ void ffma2(unsigned long long& acc,
                                      unsigned long long a,
                                      unsigned long long b) {
    asm("fma.rn.f32x2 %0, %1, %2, %0;" : "+l"(acc) : "l"(a), "l"(b));
}

// ---------------- GEMM tile body: Out = (In @ W) [* dinv[row]] -------------
// In_sT: transposed input tile -> LDS.64 gives a row-pair {a_r, a_r+1}.
// Ws2:   duplicated weights {w,w}  -> LDS.64 gives the FFMA2 multiplier.
// Columns are assigned lane-strided (c = lane + 32*t) for conflict-free LDS.
template <int K, int M, bool PRESCALE>
__device__ __forceinline__ void gemm_tile(const float* __restrict__ In,
                                          const float* __restrict__ W,
                                          float* __restrict__ Out,
                                          int n, int bid) {
    constexpr int NLG = (M >= 32) ? 1 : (32 / M);   // lane groups (M=16 -> 2)
    constexpr int TC  = (M >= 32) ? (M / 32) : 1;   // cols per lane
    constexpr int RW  = 8 * NLG;                    // rows per warp
    constexpr int BM  = 8 * RW;                     // rows per block (8 warps)
    constexpr int BK  = (M >= 128) ? 8 : 16;        // W-chunk (fit 48KB static)
    constexpr int LDT = BM + 2;                     // even -> 8B-aligned pairs

    __shared__ float In_sT[K][LDT];
    __shared__ float Ws2[BK][2 * M];

    const int tid  = threadIdx.x;
    const int row0 = bid * BM;

    // Load input tile, transposed (vectorized global read, scalar STS)
    constexpr int K4 = K / 4;
    for (int idx = tid; idx < BM * K4; idx += 256) {
        int r = idx / K4, c4 = idx % K4;
        int gr = row0 + r;
        float4 v = make_float4(0.f, 0.f, 0.f, 0.f);
        if (gr < n) v = *(const float4*)(In + (size_t)gr * K + c4 * 4);
        In_sT[c4 * 4 + 0][r] = v.x;
        In_sT[c4 * 4 + 1][r] = v.y;
        In_sT[c4 * 4 + 2][r] = v.z;
        In_sT[c4 * 4 + 3][r] = v.w;
    }

    const int warp = tid >> 5, lane = tid & 31;
    const int r0 = warp * RW + ((NLG > 1) ? (lane / M) * 8 : 0);
    const int c0 = (NLG > 1) ? (lane % M) : lane;

    unsigned long long acc[4][TC];
#pragma unroll
    for (int p = 0; p < 4; p++)
#pragma unroll
        for (int t = 0; t < TC; t++) acc[p][t] = 0ULL;

    for (int kk = 0; kk < K; kk += BK) {
        __syncthreads();  // Ws2 reuse; first iter also covers In_sT
        for (int idx = tid; idx < BK * M; idx += 256) {
            int k = idx / M, c = idx % M;
            float w = W[(size_t)(kk + k) * M + c];
            *(float2*)&Ws2[k][2 * c] = make_float2(w, w);
        }
        __syncthreads();
#pragma unroll
        for (int k = 0; k < BK; k++) {
            unsigned long long a[4], w[TC];
#pragma unroll
            for (int p = 0; p < 4; p++)
                a[p] = *(const unsigned long long*)&In_sT[kk + k][r0 + 2 * p];
#pragma unroll
            for (int t = 0; t < TC; t++)
                w[t] = *(const unsigned long long*)&Ws2[k][2 * (c0 + 32 * t)];
#pragma unroll
            for (int p = 0; p < 4; p++)
#pragma unroll
                for (int t = 0; t < TC; t++) ffma2(acc[p][t], a[p], w[t]);
        }
    }

    // Epilogue: unpack pairs, optional dinv prescale, scalar coalesced stores.
#pragma unroll
    for (int p = 0; p < 4; p++) {
        int gr = row0 + r0 + 2 * p;
#pragma unroll
        for (int half = 0; half < 2; half++) {
            int g = gr + half;
            if (g < n) {
                float sc = PRESCALE ? g_dinv[g] : 1.0f;
#pragma unroll
                for (int t = 0; t < TC; t++) {
                    float2 f2;
                    memcpy(&f2, &acc[p][t], 8);
                    float val = half ? f2.y : f2.x;
                    Out[(size_t)g * M + c0 + 32 * t] = val * sc;
                }
            }
        }
    }
}

template <int K, int M, bool PRESCALE>
__global__ __launch_bounds__(256)
void k_gemm(const float* __restrict__ In, const float* __restrict__ W,
            float* __restrict__ Out, int n) {
    gemm_tile<K, M, PRESCALE>(In, W, Out, n, blockIdx.x);
}

// ---------------- K1: GEMM1 (unscaled) fused with edge counting ------------
__global__ __launch_bounds__(256)
void k_gemm1_count(const float* __restrict__ x, const float* __restrict__ W1,
                   float* __restrict__ H, int n,
                   const int* __restrict__ dst, int e, int gemm_blocks) {
    if ((int)blockIdx.x < gemm_blocks) {
        gemm_tile<128, 128, false>(x, W1, H, n, blockIdx.x);
    } else {
        int i = ((int)blockIdx.x - gemm_blocks) * 256 + threadIdx.x;
        if (i < e) atomicAdd(&g_cnt[dst[i]], 1);
    }
}

// ---------------- K2: single-kernel scan (publish/poll, 49 resident blocks)
// Produces rowptr (exclusive prefix), wptr, dinv; re-zeroes cnt and its own
// coordination state for the next launch.
__global__ __launch_bounds__(1024)
void k_scan_fused(int n, int nb) {
    __shared__ int sh[1024];
    __shared__ int s_part[64];
    __shared__ int s_off;

    const int bid = blockIdx.x, tid = threadIdx.x;
    const int i = bid * 1024 + tid;
    int v = (i < n) ? g_cnt[i] : 0;
    sh[tid] = v;
    __syncthreads();
    for (int off = 1; off < 1024; off <<= 1) {
        int t = (tid >= off) ? sh[tid - off] : 0;
        __syncthreads();
        sh[tid] += t;
        __syncthreads();
    }
    const int tot = sh[1023];
    const int ex  = sh[tid] - v;

    // Publish this block's total (payload is the atomic value; +1 marks ready)
    if (tid == 0) atomicExch((int*)&g_btot[bid], tot + 1);

    // Poll all predecessors in parallel (<= 48 of them, all blocks resident)
    if (tid < bid) {
        int val;
        do { val = atomicAdd((int*)&g_btot[tid], 0); } while (val == 0);
        s_part[tid] = val - 1;
    }
    __syncthreads();
    if (tid == 0) {
        int off = 0;
        for (int b = 0; b < bid; b++) off += s_part[b];
        s_off = off;
    }
    __syncthreads();
    const int off = s_off;

    if (i < n) {
        int rp = off + ex;
        g_rowptr[i] = rp;
        g_wptr[i]   = rp;
        g_dinv[i]   = rsqrtf((float)v + 1.0f);  // +1 self loop
        g_cnt[i]    = 0;                        // reset for next launch
    }
    if (bid == nb - 1 && tid == 1023) g_rowptr[n] = off + tot;  // == e

    // Cleanup: last block to finish resets coordination state.
    __syncthreads();
    if (tid == 0) {
        int d = atomicAdd(&g_bdone, 1);
        if (d == nb - 1) {
            for (int b = 0; b < nb; b++) g_btot[b] = 0;
            g_bdone = 0;
        }
    }
}

// ---------------- K3: CSR fill ---------------------------------------------
__global__ void k_fill(const int* __restrict__ src, const int* __restrict__ dst, int e) {
    int i = blockIdx.x * blockDim.x + threadIdx.x;
    if (i < e) {
        int s = src[i];
        int d = dst[i];
        int idx = atomicAdd(&g_wptr[d], 1);
        g_esrc[idx] = s;
    }
}

// ---------------- Aggregation (gather-based segment sum) -------------------
// GATHER=true  : H is raw h;  out[d] = dd*(sum h[s]*dinv[s] + dd*h[d]) + b
// GATHER=false : H is h*dinv; out[d] = dd*(sum H'[s]       +    H'[d]) + b
template <int M, bool RELU, bool GATHER>
__global__ __launch_bounds__(256)
void agg_kernel(const float* __restrict__ H, const float* __restrict__ bias,
                float* __restrict__ Out, int n) {
    constexpr int NPW = (M >= 32) ? 1 : (32 / M);
    constexpr int CT  = (M >= 128) ? 4 : (M >= 64) ? 2 : 1;

    int gwarp = (blockIdx.x * blockDim.x + threadIdx.x) >> 5;
    int lane  = threadIdx.x & 31;

    int d, c0;
    if constexpr (NPW == 1) {
        d  = gwarp;
        c0 = lane * CT;
    } else {
        d  = gwarp * NPW + lane / M;
        c0 = lane % M;
    }
    if (d >= n) return;

    const float dd = g_dinv[d];
    const float selfmul = GATHER ? dd : 1.0f;

    float acc[CT];
    {
        const float* hd = H + (size_t)d * M + c0;
        if constexpr (CT == 4) {
            float4 hv = *(const float4*)hd;
            acc[0] = hv.x * selfmul; acc[1] = hv.y * selfmul;
            acc[2] = hv.z * selfmul; acc[3] = hv.w * selfmul;
        } else if constexpr (CT == 2) {
            float2 hv = *(const float2*)hd;
            acc[0] = hv.x * selfmul; acc[1] = hv.y * selfmul;
        } else {
            acc[0] = hd[0] * selfmul;
        }
    }

    const int jb = g_rowptr[d], je = g_rowptr[d + 1];
    int j = jb;
    for (; j + 4 <= je; j += 4) {
        int s0 = g_esrc[j + 0], s1 = g_esrc[j + 1];
        int s2 = g_esrc[j + 2], s3 = g_esrc[j + 3];
        float c0f = 1.f, c1f = 1.f, c2f = 1.f, c3f = 1.f;
        if constexpr (GATHER) {
            c0f = g_dinv[s0]; c1f = g_dinv[s1];
            c2f = g_dinv[s2]; c3f = g_dinv[s3];
        }
        const float* h0 = H + (size_t)s0 * M + c0;
        const float* h1 = H + (size_t)s1 * M + c0;
        const float* h2 = H + (size_t)s2 * M + c0;
        const float* h3 = H + (size_t)s3 * M + c0;
        if constexpr (CT == 4) {
            float4 v0 = *(const float4*)h0;
            float4 v1 = *(const float4*)h1;
            float4 v2 = *(const float4*)h2;
            float4 v3 = *(const float4*)h3;
            if constexpr (GATHER) {
                acc[0] += v0.x * c0f + v1.x * c1f + v2.x * c2f + v3.x * c3f;
                acc[1] += v0.y * c0f + v1.y * c1f + v2.y * c2f + v3.y * c3f;
                acc[2] += v0.z * c0f + v1.z * c1f + v2.z * c2f + v3.z * c3f;
                acc[3] += v0.w * c0f + v1.w * c1f + v2.w * c2f + v3.w * c3f;
            } else {
                acc[0] += (v0.x + v1.x) + (v2.x + v3.x);
                acc[1] += (v0.y + v1.y) + (v2.y + v3.y);
                acc[2] += (v0.z + v1.z) + (v2.z + v3.z);
                acc[3] += (v0.w + v1.w) + (v2.w + v3.w);
            }
        } else if constexpr (CT == 2) {
            float2 v0 = *(const float2*)h0;
            float2 v1 = *(const float2*)h1;
            float2 v2 = *(const float2*)h2;
            float2 v3 = *(const float2*)h3;
            if constexpr (GATHER) {
                acc[0] += v0.x * c0f + v1.x * c1f + v2.x * c2f + v3.x * c3f;
                acc[1] += v0.y * c0f + v1.y * c1f + v2.y * c2f + v3.y * c3f;
            } else {
                acc[0] += (v0.x + v1.x) + (v2.x + v3.x);
                acc[1] += (v0.y + v1.y) + (v2.y + v3.y);
            }
        } else {
            float v0 = h0[0], v1 = h1[0], v2 = h2[0], v3 = h3[0];
            if constexpr (GATHER) {
                acc[0] += v0 * c0f + v1 * c1f + v2 * c2f + v3 * c3f;
            } else {
                acc[0] += (v0 + v1) + (v2 + v3);
            }
        }
    }
    for (; j < je; j++) {
        int s = g_esrc[j];
        float cf = GATHER ? g_dinv[s] : 1.0f;
        const float* hs = H + (size_t)s * M + c0;
        if constexpr (CT == 4) {
            float4 v = *(const float4*)hs;
            acc[0] += v.x * cf; acc[1] += v.y * cf;
            acc[2] += v.z * cf; acc[3] += v.w * cf;
        } else if constexpr (CT == 2) {
            float2 v = *(const float2*)hs;
            acc[0] += v.x * cf; acc[1] += v.y * cf;
        } else {
            acc[0] += hs[0] * cf;
        }
    }

#pragma unroll
    for (int t = 0; t < CT; t++) {
        float r = acc[t] * dd + bias[c0 + t];
        acc[t] = RELU ? fmaxf(r, 0.f) : r;
    }

    float* od = Out + (size_t)d * M + c0;
    if constexpr (CT == 4) {
        *(float4*)od = make_float4(acc[0], acc[1], acc[2], acc[3]);
    } else if constexpr (CT == 2) {
        *(float2*)od = make_float2(acc[0], acc[1]);
    } else {
        od[0] = acc[0];
    }
}

// ---------------- launcher -------------------------------------------------
extern "C" void kernel_launch(void* const* d_in, const int* in_sizes, int n_in,
                              void* d_out, int out_size) {
    const float* x  = (const float*)d_in[0];
    const int*   ei = (const int*)d_in[1];   // [2, E] int32
    const float* W1 = (const float*)d_in[2];
    const float* b1 = (const float*)d_in[3];
    const float* W2 = (const float*)d_in[4];
    const float* b2 = (const float*)d_in[5];
    const float* W3 = (const float*)d_in[6];
    const float* b3 = (const float*)d_in[7];

    const int n = in_sizes[0] / 128;
    const int e = in_sizes[1] / 2;
    const int* src = ei;
    const int* dst = ei + e;

    void *pH = nullptr, *pA = nullptr;
    cudaGetSymbolAddress(&pH, g_H);
    cudaGetSymbolAddress(&pA, g_A);
    float* H = (float*)pH;
    float* A = (float*)pA;
    float* out = (float*)d_out;

    const int ge  = (e + 255) / 256;
    const int gb1 = (n + 63) / 64;
    const int nb  = (n + 1023) / 1024;   // 49, <= 64

    // K1: GEMM1 (x@W1, unscaled) with edge counting fused in spare blocks
    k_gemm1_count<<<gb1 + ge, 256>>>(x, W1, H, n, dst, e, gb1);
    // K2: single-kernel scan -> rowptr/wptr/dinv (+ cnt reset)
    k_scan_fused<<<nb, 1024>>>(n, nb);
    // K3: CSR fill
    k_fill<<<ge, 256>>>(src, dst, e);
    // K4: layer-1 aggregation (per-edge dinv gather), ReLU
    agg_kernel<128, true, true><<<(n + 7) / 8, 256>>>(H, b1, A, n);

    // Layer 2: 128 -> 64 (prescaled GEMM epilogue), ReLU
    k_gemm<128, 64, true><<<(n + 63) / 64, 256>>>(A, W2, H, n);
    agg_kernel<64, true, false><<<(n + 7) / 8, 256>>>(H, b2, A, n);

    // Layer 3: 64 -> 16 (prescaled)
    k_gemm<64, 16, true><<<(n + 127) / 128, 256>>>(A, W3, H, n);
    {
        const int NPW = 2;  // 16-wide rows, 2 nodes per warp
        int warps  = (n + NPW - 1) / NPW;
        int blocks = (warps * 32 + 255) / 256;
        agg_kernel<16, false, false><<<blocks, 256>>>(H, b3, out, n);
    }
}

// round 8
// speedup vs baseline: 1.4486x; 1.4486x over previous
#include <cuda_runtime.h>
#include <cuda_bf16.h>
#include <cstdint>

// Problem constants (fixed by dataset; runtime values read from in_sizes).
#define NMAX 50000
#define EMAX 600000

// ---------------- scratch (device globals; no allocation allowed) ----------
// All mutable state is rebuilt every launch; counters/flags are returned to
// zero at the end of each launch -> deterministic across graph replays.
__device__ int   g_cnt[NMAX];
__device__ int   g_rowptr[NMAX + 1];
__device__ int   g_wptr[NMAX];
__device__ int   g_esrc[EMAX];
__device__ float g_dinv[NMAX];
__device__ float g_H[(size_t)NMAX * 128];
__device__ float g_A[(size_t)NMAX * 128];
__device__ volatile int g_btot[64];   // scan block totals (+1 = published)
__device__ int   g_bdone;             // scan completion counter

// ---------------- helpers --------------------------------------------------
__device__ __forceinline__ uint32_t f2tf32(float f) {
    uint32_t u;
    asm("cvt.rna.tf32.f32 %0, %1;" : "=r"(u) : "f"(f));
    return u;
}

__device__ __forceinline__ void mma_tf32(float c[4],
                                         uint32_t a0, uint32_t a1,
                                         uint32_t a2, uint32_t a3,
                                         uint32_t b0, uint32_t b1) {
    asm volatile(
        "mma.sync.aligned.m16n8k8.row.col.f32.tf32.tf32.f32 "
        "{%0,%1,%2,%3}, {%4,%5,%6,%7}, {%8,%9}, {%0,%1,%2,%3};"
        : "+f"(c[0]), "+f"(c[1]), "+f"(c[2]), "+f"(c[3])
        : "r"(a0), "r"(a1), "r"(a2), "r"(a3), "r"(b0), "r"(b1));
}

// ---------------- CSR build ------------------------------------------------
__global__ void k_count(const int* __restrict__ dst, int e) {
    int i = blockIdx.x * blockDim.x + threadIdx.x;
    if (i < e) atomicAdd(&g_cnt[dst[i]], 1);
}

// Single-kernel scan (publish/poll; all 49 blocks co-resident).
// Produces rowptr/wptr/dinv; re-zeroes cnt and its own coordination state.
__global__ __launch_bounds__(1024)
void k_scan_fused(int n, int nb) {
    __shared__ int sh[1024];
    __shared__ int s_part[64];
    __shared__ int s_off;

    const int bid = blockIdx.x, tid = threadIdx.x;
    const int i = bid * 1024 + tid;
    int v = (i < n) ? g_cnt[i] : 0;
    sh[tid] = v;
    __syncthreads();
    for (int off = 1; off < 1024; off <<= 1) {
        int t = (tid >= off) ? sh[tid - off] : 0;
        __syncthreads();
        sh[tid] += t;
        __syncthreads();
    }
    const int tot = sh[1023];
    const int ex  = sh[tid] - v;

    if (tid == 0) atomicExch((int*)&g_btot[bid], tot + 1);

    if (tid < bid) {
        int val;
        do { val = atomicAdd((int*)&g_btot[tid], 0); } while (val == 0);
        s_part[tid] = val - 1;
    }
    __syncthreads();
    if (tid == 0) {
        int off = 0;
        for (int b = 0; b < bid; b++) off += s_part[b];
        s_off = off;
    }
    __syncthreads();
    const int off = s_off;

    if (i < n) {
        int rp = off + ex;
        g_rowptr[i] = rp;
        g_wptr[i]   = rp;
        g_dinv[i]   = rsqrtf((float)v + 1.0f);  // +1 self loop
        g_cnt[i]    = 0;                        // reset for next launch
    }
    if (bid == nb - 1 && tid == 1023) g_rowptr[n] = off + tot;  // == e

    __syncthreads();
    if (tid == 0) {
        int d = atomicAdd(&g_bdone, 1);
        if (d == nb - 1) {
            for (int b = 0; b < nb; b++) g_btot[b] = 0;
            g_bdone = 0;
        }
    }
}

__global__ void k_fill(const int* __restrict__ src, const int* __restrict__ dst, int e) {
    int i = blockIdx.x * blockDim.x + threadIdx.x;
    if (i < e) {
        int s = src[i];
        int d = dst[i];
        int idx = atomicAdd(&g_wptr[d], 1);
        g_esrc[idx] = s;
    }
}

// ---------------- tf32 tensor-core GEMM ------------------------------------
// Out[n,M] = (In[n,K] @ W[K,M]) * dinv[row]
// Block: 256 threads = 8 warps; 128 rows/block, 16 rows/warp, full M width.
// K chunked by 32. A staged as tf32 in In_s[128][36]; W staged TRANSPOSED
// (WsT[col][k]) so both A and B fragment LDS are conflict-free:
//   bank(In_s[r][k])   = (r*4 + k) & 31  -> 32 distinct lanes
//   bank(WsT[c][k])    = (c*4 + k) & 31  -> 32 distinct lanes
template <int K, int M>
__global__ __launch_bounds__(256)
void k_gemm_tc(const float* __restrict__ In, const float* __restrict__ W,
               float* __restrict__ Out, int n) {
    constexpr int NG = M / 8;       // n-groups of 8 columns
    constexpr int KC = 32;          // K chunk

    __shared__ uint32_t In_s[128][36];
    __shared__ uint32_t WsT[M][36];

    const int tid  = threadIdx.x;
    const int warp = tid >> 5, lane = tid & 31;
    const int gid  = lane >> 2;     // 0..7
    const int tig  = lane & 3;      // 0..3
    const int row0 = blockIdx.x * 128;
    const int rw   = warp * 16;     // warp's first row within block

    float acc[NG][4];
#pragma unroll
    for (int g = 0; g < NG; g++)
#pragma unroll
        for (int t = 0; t < 4; t++) acc[g][t] = 0.f;

    for (int kk = 0; kk < K; kk += KC) {
        // ---- stage A chunk (rows x 32k), converted to tf32 ----
        for (int idx = tid; idx < 128 * 8; idx += 256) {
            int r = idx >> 3, c4 = idx & 7;
            int gr = row0 + r;
            float4 v = make_float4(0.f, 0.f, 0.f, 0.f);
            if (gr < n) v = *(const float4*)(In + (size_t)gr * K + kk + c4 * 4);
            uint32_t* p = &In_s[r][c4 * 4];
            p[0] = f2tf32(v.x); p[1] = f2tf32(v.y);
            p[2] = f2tf32(v.z); p[3] = f2tf32(v.w);
        }
        // ---- stage W chunk transposed (WsT[col][k]) ----
        for (int idx = tid; idx < KC * (M / 4); idx += 256) {
            int k = idx / (M / 4), c4 = idx % (M / 4);
            float4 w = *(const float4*)(W + (size_t)(kk + k) * M + c4 * 4);
            WsT[c4 * 4 + 0][k] = f2tf32(w.x);
            WsT[c4 * 4 + 1][k] = f2tf32(w.y);
            WsT[c4 * 4 + 2][k] = f2tf32(w.z);
            WsT[c4 * 4 + 3][k] = f2tf32(w.w);
        }
        __syncthreads();

#pragma unroll
        for (int k8 = 0; k8 < KC / 8; k8++) {
            const int kb = k8 * 8;
            uint32_t a0 = In_s[rw + gid    ][kb + tig];
            uint32_t a1 = In_s[rw + gid + 8][kb + tig];
            uint32_t a2 = In_s[rw + gid    ][kb + tig + 4];
            uint32_t a3 = In_s[rw + gid + 8][kb + tig + 4];
#pragma unroll
            for (int g = 0; g < NG; g++) {
                uint32_t b0 = WsT[g * 8 + gid][kb + tig];
                uint32_t b1 = WsT[g * 8 + gid][kb + tig + 4];
                mma_tf32(acc[g], a0, a1, a2, a3, b0, b1);
            }
        }
        __syncthreads();
    }

    // ---- epilogue: scale by dinv[row], float2 stores ----
    const int ra = row0 + rw + gid;
    const int rb = ra + 8;
    const float sa = (ra < n) ? g_dinv[ra] : 0.f;
    const float sb = (rb < n) ? g_dinv[rb] : 0.f;
#pragma unroll
    for (int g = 0; g < NG; g++) {
        int col = g * 8 + tig * 2;
        if (ra < n)
            *(float2*)(Out + (size_t)ra * M + col) =
                make_float2(acc[g][0] * sa, acc[g][1] * sa);
        if (rb < n)
            *(float2*)(Out + (size_t)rb * M + col) =
                make_float2(acc[g][2] * sb, acc[g][3] * sb);
    }
}

// ---------------- Aggregation (gather-based segment sum) -------------------
// H is pre-scaled: H'[i] = h[i]*dinv[i].
//   out[d] = dinv[d] * ( sum_{e: dst=d} H'[src_e] + H'[d] ) + b
template <int M, bool RELU>
__global__ __launch_bounds__(256)
void agg_kernel(const float* __restrict__ H, const float* __restrict__ bias,
                float* __restrict__ Out, int n) {
    constexpr int NPW = (M >= 32) ? 1 : (32 / M);
    constexpr int CT  = (M >= 128) ? 4 : (M >= 64) ? 2 : 1;

    int gwarp = (blockIdx.x * blockDim.x + threadIdx.x) >> 5;
    int lane  = threadIdx.x & 31;

    int d, c0;
    if constexpr (NPW == 1) {
        d  = gwarp;
        c0 = lane * CT;
    } else {
        d  = gwarp * NPW + lane / M;
        c0 = lane % M;
    }
    if (d >= n) return;

    const float dd = g_dinv[d];

    float acc[CT];
    {
        const float* hd = H + (size_t)d * M + c0;  // self loop
        if constexpr (CT == 4) {
            float4 hv = *(const float4*)hd;
            acc[0] = hv.x; acc[1] = hv.y; acc[2] = hv.z; acc[3] = hv.w;
        } else if constexpr (CT == 2) {
            float2 hv = *(const float2*)hd;
            acc[0] = hv.x; acc[1] = hv.y;
        } else {
            acc[0] = hd[0];
        }
    }

    const int jb = g_rowptr[d], je = g_rowptr[d + 1];
    int j = jb;
    for (; j + 4 <= je; j += 4) {
        int s0 = g_esrc[j + 0], s1 = g_esrc[j + 1];
        int s2 = g_esrc[j + 2], s3 = g_esrc[j + 3];
        const float* h0 = H + (size_t)s0 * M + c0;
        const float* h1 = H + (size_t)s1 * M + c0;
        const float* h2 = H + (size_t)s2 * M + c0;
        const float* h3 = H + (size_t)s3 * M + c0;
        if constexpr (CT == 4) {
            float4 v0 = *(const float4*)h0;
            float4 v1 = *(const float4*)h1;
            float4 v2 = *(const float4*)h2;
            float4 v3 = *(const float4*)h3;
            acc[0] += (v0.x + v1.x) + (v2.x + v3.x);
            acc[1] += (v0.y + v1.y) + (v2.y + v3.y);
            acc[2] += (v0.z + v1.z) + (v2.z + v3.z);
            acc[3] += (v0.w + v1.w) + (v2.w + v3.w);
        } else if constexpr (CT == 2) {
            float2 v0 = *(const float2*)h0;
            float2 v1 = *(const float2*)h1;
            float2 v2 = *(const float2*)h2;
            float2 v3 = *(const float2*)h3;
            acc[0] += (v0.x + v1.x) + (v2.x + v3.x);
            acc[1] += (v0.y + v1.y) + (v2.y + v3.y);
        } else {
            float v0 = h0[0], v1 = h1[0], v2 = h2[0], v3 = h3[0];
            acc[0] += (v0 + v1) + (v2 + v3);
        }
    }
    for (; j < je; j++) {
        int s = g_esrc[j];
        const float* hs = H + (size_t)s * M + c0;
        if constexpr (CT == 4) {
            float4 v = *(const float4*)hs;
            acc[0] += v.x; acc[1] += v.y; acc[2] += v.z; acc[3] += v.w;
        } else if constexpr (CT == 2) {
            float2 v = *(const float2*)hs;
            acc[0] += v.x; acc[1] += v.y;
        } else {
            acc[0] += hs[0];
        }
    }

#pragma unroll
    for (int t = 0; t < CT; t++) {
        float r = acc[t] * dd + bias[c0 + t];
        acc[t] = RELU ? fmaxf(r, 0.f) : r;
    }

    float* od = Out + (size_t)d * M + c0;
    if constexpr (CT == 4) {
        *(float4*)od = make_float4(acc[0], acc[1], acc[2], acc[3]);
    } else if constexpr (CT == 2) {
        *(float2*)od = make_float2(acc[0], acc[1]);
    } else {
        od[0] = acc[0];
    }
}

// ---------------- launcher -------------------------------------------------
extern "C" void kernel_launch(void* const* d_in, const int* in_sizes, int n_in,
                              void* d_out, int out_size) {
    const float* x  = (const float*)d_in[0];
    const int*   ei = (const int*)d_in[1];   // [2, E] int32
    const float* W1 = (const float*)d_in[2];
    const float* b1 = (const float*)d_in[3];
    const float* W2 = (const float*)d_in[4];
    const float* b2 = (const float*)d_in[5];
    const float* W3 = (const float*)d_in[6];
    const float* b3 = (const float*)d_in[7];

    const int n = in_sizes[0] / 128;
    const int e = in_sizes[1] / 2;
    const int* src = ei;
    const int* dst = ei + e;

    void *pH = nullptr, *pA = nullptr;
    cudaGetSymbolAddress(&pH, g_H);
    cudaGetSymbolAddress(&pA, g_A);
    float* H = (float*)pH;
    float* A = (float*)pA;
    float* out = (float*)d_out;

    const int ge = (e + 255) / 256;
    const int nb = (n + 1023) / 1024;    // 49 <= 64
    const int gg = (n + 127) / 128;      // GEMM blocks

    // CSR build (dinv ready before GEMM1 so all GEMMs prescale)
    k_count<<<ge, 256>>>(dst, e);
    k_scan_fused<<<nb, 1024>>>(n, nb);
    k_fill<<<ge, 256>>>(src, dst, e);

    // Layer 1: 128 -> 128, ReLU
    k_gemm_tc<128, 128><<<gg, 256>>>(x, W1, H, n);
    agg_kernel<128, true><<<(n + 7) / 8, 256>>>(H, b1, A, n);

    // Layer 2: 128 -> 64, ReLU
    k_gemm_tc<128, 64><<<gg, 256>>>(A, W2, H, n);
    agg_kernel<64, true><<<(n + 7) / 8, 256>>>(H, b2, A, n);

    // Layer 3: 64 -> 16
    k_gemm_tc<64, 16><<<gg, 256>>>(A, W3, H, n);
    {
        const int NPW = 2;  // 16-wide rows, 2 nodes per warp
        int warps  = (n + NPW - 1) / NPW;
        int blocks = (warps * 32 + 255) / 256;
        agg_kernel<16, false><<<blocks, 256>>>(H, b3, out, n);
    }
}

// round 9
// speedup vs baseline: 1.6812x; 1.1605x over previous
#include <cuda_runtime.h>
#include <cuda_bf16.h>
#include <cstdint>

// Problem constants (fixed by dataset; runtime values read from in_sizes).
#define NMAX 50000
#define EMAX 600000

// ---------------- scratch (device globals; no allocation allowed) ----------
// All mutable state is rebuilt every launch; counters/flags are returned to
// zero at the end of each launch -> deterministic across graph replays.
__device__ int   g_cnt[NMAX];
__device__ int   g_rowptr[NMAX + 1];
__device__ int   g_wptr[NMAX];
__device__ int   g_esrc[EMAX];
__device__ float g_dinv[NMAX];
__device__ float g_H[(size_t)NMAX * 128];
__device__ float g_A[(size_t)NMAX * 128];
__device__ volatile int g_btot[64];   // scan block totals (+1 = published)
__device__ int   g_bdone;             // scan completion counter

// ---------------- helpers --------------------------------------------------
__device__ __forceinline__ uint32_t f2tf32(float f) {
    uint32_t u;
    asm("cvt.rna.tf32.f32 %0, %1;" : "=r"(u) : "f"(f));
    return u;
}

__device__ __forceinline__ void mma_tf32(float c[4],
                                         uint32_t a0, uint32_t a1,
                                         uint32_t a2, uint32_t a3,
                                         uint32_t b0, uint32_t b1) {
    asm volatile(
        "mma.sync.aligned.m16n8k8.row.col.f32.tf32.tf32.f32 "
        "{%0,%1,%2,%3}, {%4,%5,%6,%7}, {%8,%9}, {%0,%1,%2,%3};"
        : "+f"(c[0]), "+f"(c[1]), "+f"(c[2]), "+f"(c[3])
        : "r"(a0), "r"(a1), "r"(a2), "r"(a3), "r"(b0), "r"(b1));
}

// ---------------- CSR build ------------------------------------------------
__global__ void k_count(const int* __restrict__ dst, int e) {
    int i = blockIdx.x * blockDim.x + threadIdx.x;
    if (i < e) atomicAdd(&g_cnt[dst[i]], 1);
}

// Single-kernel scan (publish/poll; all 49 blocks co-resident).
__global__ __launch_bounds__(1024)
void k_scan_fused(int n, int nb) {
    __shared__ int sh[1024];
    __shared__ int s_part[64];
    __shared__ int s_off;

    const int bid = blockIdx.x, tid = threadIdx.x;
    const int i = bid * 1024 + tid;
    int v = (i < n) ? g_cnt[i] : 0;
    sh[tid] = v;
    __syncthreads();
    for (int off = 1; off < 1024; off <<= 1) {
        int t = (tid >= off) ? sh[tid - off] : 0;
        __syncthreads();
        sh[tid] += t;
        __syncthreads();
    }
    const int tot = sh[1023];
    const int ex  = sh[tid] - v;

    if (tid == 0) atomicExch((int*)&g_btot[bid], tot + 1);

    if (tid < bid) {
        int val;
        do { val = atomicAdd((int*)&g_btot[tid], 0); } while (val == 0);
        s_part[tid] = val - 1;
    }
    __syncthreads();
    if (tid == 0) {
        int off = 0;
        for (int b = 0; b < bid; b++) off += s_part[b];
        s_off = off;
    }
    __syncthreads();
    const int off = s_off;

    if (i < n) {
        int rp = off + ex;
        g_rowptr[i] = rp;
        g_wptr[i]   = rp;
        g_dinv[i]   = rsqrtf((float)v + 1.0f);  // +1 self loop
        g_cnt[i]    = 0;                        // reset for next launch
    }
    if (bid == nb - 1 && tid == 1023) g_rowptr[n] = off + tot;  // == e

    __syncthreads();
    if (tid == 0) {
        int d = atomicAdd(&g_bdone, 1);
        if (d == nb - 1) {
            for (int b = 0; b < nb; b++) g_btot[b] = 0;
            g_bdone = 0;
        }
    }
}

__global__ void k_fill(const int* __restrict__ src, const int* __restrict__ dst, int e) {
    int i = blockIdx.x * blockDim.x + threadIdx.x;
    if (i < e) {
        int s = src[i];
        int d = dst[i];
        int idx = atomicAdd(&g_wptr[d], 1);
        g_esrc[idx] = s;
    }
}

// ---------------- tf32 tensor-core GEMM, paired-fragment layout ------------
// Out[n,M] = (In[n,K] @ W[K,M]) * dinv[row]
//
// Fragments for k and k+4 are stored adjacent as uint2, so each A/B fragment
// pair is ONE LDS.64. Row stride 20 uint2 (=40 words): word = r*40 + tig*2
// -> banks gid*8 + tig*2 (+1) cover all 32 banks per half-warp phase.
//
// Warp tile: 32 rows x (NG*8) cols (two m16 row-tiles share B fragments).
//   M=128: 4x2 warp grid, BM=128, NG=8
//   M= 64: 4x2 warp grid, BM=128, NG=4
//   M= 16: 8x1 warp grid, BM=256, NG=2
template <int K, int M>
__global__ __launch_bounds__(256)
void k_gemm_tc(const float* __restrict__ In, const float* __restrict__ W,
               float* __restrict__ Out, int n) {
    constexpr int WC = (M >= 64) ? 2 : 1;       // warp cols groups
    constexpr int NG = M / (8 * WC);            // 8-col groups per warp
    constexpr int WR = 8 / WC;                  // warp row groups
    constexpr int BM = WR * 32;                 // rows per block
    constexpr int KC = 32;                      // K chunk
    constexpr int LD = 20;                      // uint2 per row (16 + 4 pad)

    __shared__ uint2 Ap[BM][LD];
    __shared__ uint2 Bp[M][LD];

    const int tid  = threadIdx.x;
    const int warp = tid >> 5, lane = tid & 31;
    const int gid  = lane >> 2;                 // 0..7
    const int tig  = lane & 3;                  // 0..3
    const int row0 = blockIdx.x * BM;
    const int wr   = (WC == 2) ? (warp >> 1) : warp;   // row group
    const int wc   = (WC == 2) ? (warp & 1) : 0;       // col group
    const int rbase = wr * 32;
    const int cbase = wc * NG * 8;

    float acc[2][NG][4];
#pragma unroll
    for (int rt = 0; rt < 2; rt++)
#pragma unroll
        for (int g = 0; g < NG; g++)
#pragma unroll
            for (int t = 0; t < 4; t++) acc[rt][g][t] = 0.f;

    for (int kk = 0; kk < K; kk += KC) {
        // ---- stage A chunk: Ap[r][k8*4+tig] = {tf32(k), tf32(k+4)} ----
        for (int idx = tid; idx < BM * 4; idx += 256) {
            int r = idx >> 2, k8 = idx & 3;
            int gr = row0 + r;
            float4 v0 = make_float4(0.f, 0.f, 0.f, 0.f);
            float4 v1 = v0;
            if (gr < n) {
                const float* p = In + (size_t)gr * K + kk + k8 * 8;
                v0 = *(const float4*)p;
                v1 = *(const float4*)(p + 4);
            }
            uint2* q = &Ap[r][k8 * 4];
            q[0] = make_uint2(f2tf32(v0.x), f2tf32(v1.x));
            q[1] = make_uint2(f2tf32(v0.y), f2tf32(v1.y));
            q[2] = make_uint2(f2tf32(v0.z), f2tf32(v1.z));
            q[3] = make_uint2(f2tf32(v0.w), f2tf32(v1.w));
        }
        // ---- stage B chunk transposed+paired: Bp[c][k8*4+tig] ----
        for (int idx = tid; idx < M * 4; idx += 256) {
            int c = idx % M, k8 = idx / M;
            const float* p = W + (size_t)(kk + k8 * 8) * M + c;
            uint2* q = &Bp[c][k8 * 4];
#pragma unroll
            for (int t = 0; t < 4; t++)
                q[t] = make_uint2(f2tf32(p[(size_t)t * M]),
                                  f2tf32(p[(size_t)(t + 4) * M]));
        }
        __syncthreads();

#pragma unroll
        for (int k8 = 0; k8 < KC / 8; k8++) {
            const int kq = k8 * 4 + tig;
            uint2 a00 = Ap[rbase + gid     ][kq];
            uint2 a01 = Ap[rbase + gid + 8 ][kq];
            uint2 a10 = Ap[rbase + 16 + gid    ][kq];
            uint2 a11 = Ap[rbase + 16 + gid + 8][kq];
            uint2 b[NG];
#pragma unroll
            for (int g = 0; g < NG; g++) b[g] = Bp[cbase + g * 8 + gid][kq];
#pragma unroll
            for (int g = 0; g < NG; g++) {
                mma_tf32(acc[0][g], a00.x, a01.x, a00.y, a01.y, b[g].x, b[g].y);
                mma_tf32(acc[1][g], a10.x, a11.x, a10.y, a11.y, b[g].x, b[g].y);
            }
        }
        __syncthreads();
    }

    // ---- epilogue: scale by dinv[row], float2 stores ----
#pragma unroll
    for (int rt = 0; rt < 2; rt++) {
        const int ra = row0 + rbase + rt * 16 + gid;
        const int rb = ra + 8;
        const float sa = (ra < n) ? g_dinv[ra] : 0.f;
        const float sb = (rb < n) ? g_dinv[rb] : 0.f;
#pragma unroll
        for (int g = 0; g < NG; g++) {
            int col = cbase + g * 8 + tig * 2;
            if (ra < n)
                *(float2*)(Out + (size_t)ra * M + col) =
                    make_float2(acc[rt][g][0] * sa, acc[rt][g][1] * sa);
            if (rb < n)
                *(float2*)(Out + (size_t)rb * M + col) =
                    make_float2(acc[rt][g][2] * sb, acc[rt][g][3] * sb);
        }
    }
}

// ---------------- Aggregation (gather-based segment sum) -------------------
// H is pre-scaled: H'[i] = h[i]*dinv[i].
//   out[d] = dinv[d] * ( sum_{e: dst=d} H'[src_e] + H'[d] ) + b
template <int M, bool RELU>
__global__ __launch_bounds__(256)
void agg_kernel(const float* __restrict__ H, const float* __restrict__ bias,
                float* __restrict__ Out, int n) {
    constexpr int NPW = (M >= 32) ? 1 : (32 / M);
    constexpr int CT  = (M >= 128) ? 4 : (M >= 64) ? 2 : 1;

    int gwarp = (blockIdx.x * blockDim.x + threadIdx.x) >> 5;
    int lane  = threadIdx.x & 31;

    int d, c0;
    if constexpr (NPW == 1) {
        d  = gwarp;
        c0 = lane * CT;
    } else {
        d  = gwarp * NPW + lane / M;
        c0 = lane % M;
    }
    if (d >= n) return;

    const float dd = g_dinv[d];

    float acc[CT];
    {
        const float* hd = H + (size_t)d * M + c0;  // self loop
        if constexpr (CT == 4) {
            float4 hv = *(const float4*)hd;
            acc[0] = hv.x; acc[1] = hv.y; acc[2] = hv.z; acc[3] = hv.w;
        } else if constexpr (CT == 2) {
            float2 hv = *(const float2*)hd;
            acc[0] = hv.x; acc[1] = hv.y;
        } else {
            acc[0] = hd[0];
        }
    }

    const int jb = g_rowptr[d], je = g_rowptr[d + 1];
    int j = jb;
    for (; j + 4 <= je; j += 4) {
        int s0 = g_esrc[j + 0], s1 = g_esrc[j + 1];
        int s2 = g_esrc[j + 2], s3 = g_esrc[j + 3];
        const float* h0 = H + (size_t)s0 * M + c0;
        const float* h1 = H + (size_t)s1 * M + c0;
        const float* h2 = H + (size_t)s2 * M + c0;
        const float* h3 = H + (size_t)s3 * M + c0;
        if constexpr (CT == 4) {
            float4 v0 = *(const float4*)h0;
            float4 v1 = *(const float4*)h1;
            float4 v2 = *(const float4*)h2;
            float4 v3 = *(const float4*)h3;
            acc[0] += (v0.x + v1.x) + (v2.x + v3.x);
            acc[1] += (v0.y + v1.y) + (v2.y + v3.y);
            acc[2] += (v0.z + v1.z) + (v2.z + v3.z);
            acc[3] += (v0.w + v1.w) + (v2.w + v3.w);
        } else if constexpr (CT == 2) {
            float2 v0 = *(const float2*)h0;
            float2 v1 = *(const float2*)h1;
            float2 v2 = *(const float2*)h2;
            float2 v3 = *(const float2*)h3;
            acc[0] += (v0.x + v1.x) + (v2.x + v3.x);
            acc[1] += (v0.y + v1.y) + (v2.y + v3.y);
        } else {
            float v0 = h0[0], v1 = h1[0], v2 = h2[0], v3 = h3[0];
            acc[0] += (v0 + v1) + (v2 + v3);
        }
    }
    for (; j < je; j++) {
        int s = g_esrc[j];
        const float* hs = H + (size_t)s * M + c0;
        if constexpr (CT == 4) {
            float4 v = *(const float4*)hs;
            acc[0] += v.x; acc[1] += v.y; acc[2] += v.z; acc[3] += v.w;
        } else if constexpr (CT == 2) {
            float2 v = *(const float2*)hs;
            acc[0] += v.x; acc[1] += v.y;
        } else {
            acc[0] += hs[0];
        }
    }

#pragma unroll
    for (int t = 0; t < CT; t++) {
        float r = acc[t] * dd + bias[c0 + t];
        acc[t] = RELU ? fmaxf(r, 0.f) : r;
    }

    float* od = Out + (size_t)d * M + c0;
    if constexpr (CT == 4) {
        *(float4*)od = make_float4(acc[0], acc[1], acc[2], acc[3]);
    } else if constexpr (CT == 2) {
        *(float2*)od = make_float2(acc[0], acc[1]);
    } else {
        od[0] = acc[0];
    }
}

// ---------------- launcher -------------------------------------------------
extern "C" void kernel_launch(void* const* d_in, const int* in_sizes, int n_in,
                              void* d_out, int out_size) {
    const float* x  = (const float*)d_in[0];
    const int*   ei = (const int*)d_in[1];   // [2, E] int32
    const float* W1 = (const float*)d_in[2];
    const float* b1 = (const float*)d_in[3];
    const float* W2 = (const float*)d_in[4];
    const float* b2 = (const float*)d_in[5];
    const float* W3 = (const float*)d_in[6];
    const float* b3 = (const float*)d_in[7];

    const int n = in_sizes[0] / 128;
    const int e = in_sizes[1] / 2;
    const int* src = ei;
    const int* dst = ei + e;

    void *pH = nullptr, *pA = nullptr;
    cudaGetSymbolAddress(&pH, g_H);
    cudaGetSymbolAddress(&pA, g_A);
    float* H = (float*)pH;
    float* A = (float*)pA;
    float* out = (float*)d_out;

    const int ge = (e + 255) / 256;
    const int nb = (n + 1023) / 1024;    // 49 <= 64

    // CSR build (dinv ready before GEMM1 so all GEMMs prescale)
    k_count<<<ge, 256>>>(dst, e);
    k_scan_fused<<<nb, 1024>>>(n, nb);
    k_fill<<<ge, 256>>>(src, dst, e);

    // Layer 1: 128 -> 128, ReLU
    k_gemm_tc<128, 128><<<(n + 127) / 128, 256>>>(x, W1, H, n);
    agg_kernel<128, true><<<(n + 7) / 8, 256>>>(H, b1, A, n);

    // Layer 2: 128 -> 64, ReLU
    k_gemm_tc<128, 64><<<(n + 127) / 128, 256>>>(A, W2, H, n);
    agg_kernel<64, true><<<(n + 7) / 8, 256>>>(H, b2, A, n);

    // Layer 3: 64 -> 16
    k_gemm_tc<64, 16><<<(n + 255) / 256, 256>>>(A, W3, H, n);
    {
        const int NPW = 2;  // 16-wide rows, 2 nodes per warp
        int warps  = (n + NPW - 1) / NPW;
        int blocks = (warps * 32 + 255) / 256;
        agg_kernel<16, false><<<blocks, 256>>>(H, b3, out, n);
    }
}

// round 10
// speedup vs baseline: 1.7444x; 1.0376x over previous
#include <cuda_runtime.h>
#include <cuda_bf16.h>
#include <cstdint>

// Problem constants (fixed by dataset; runtime values read from in_sizes).
#define NMAX 50000
#define EMAX 600000

// ---------------- scratch (device globals; no allocation allowed) ----------
// All mutable state is rebuilt every launch; counters/flags are returned to
// zero at the end of each launch -> deterministic across graph replays.
__device__ int   g_cnt[NMAX];
__device__ int   g_rowptr[NMAX + 1];
__device__ int   g_wptr[NMAX];
__device__ int   g_esrc[EMAX];
__device__ float g_dinv[NMAX];
__device__ float g_H[(size_t)NMAX * 128];
__device__ float g_A[(size_t)NMAX * 128];
__device__ volatile int g_btot[64];   // scan block totals (+1 = published)
__device__ int   g_bdone;             // scan completion counter

// ---------------- helpers --------------------------------------------------
__device__ __forceinline__ uint32_t f2tf32(float f) {
    uint32_t u;
    asm("cvt.rna.tf32.f32 %0, %1;" : "=r"(u) : "f"(f));
    return u;
}

__device__ __forceinline__ void mma_tf32(float c[4],
                                         uint32_t a0, uint32_t a1,
                                         uint32_t a2, uint32_t a3,
                                         uint32_t b0, uint32_t b1) {
    asm volatile(
        "mma.sync.aligned.m16n8k8.row.col.f32.tf32.tf32.f32 "
        "{%0,%1,%2,%3}, {%4,%5,%6,%7}, {%8,%9}, {%0,%1,%2,%3};"
        : "+f"(c[0]), "+f"(c[1]), "+f"(c[2]), "+f"(c[3])
        : "r"(a0), "r"(a1), "r"(a2), "r"(a3), "r"(b0), "r"(b1));
}

// ---------------- CSR build ------------------------------------------------
__global__ void k_count(const int* __restrict__ dst, int e) {
    int i = blockIdx.x * blockDim.x + threadIdx.x;
    if (i < e) atomicAdd(&g_cnt[dst[i]], 1);
}

// Single-kernel scan (publish/poll; all 49 blocks co-resident).
__global__ __launch_bounds__(1024)
void k_scan_fused(int n, int nb) {
    __shared__ int sh[1024];
    __shared__ int s_part[64];
    __shared__ int s_off;

    const int bid = blockIdx.x, tid = threadIdx.x;
    const int i = bid * 1024 + tid;
    int v = (i < n) ? g_cnt[i] : 0;
    sh[tid] = v;
    __syncthreads();
    for (int off = 1; off < 1024; off <<= 1) {
        int t = (tid >= off) ? sh[tid - off] : 0;
        __syncthreads();
        sh[tid] += t;
        __syncthreads();
    }
    const int tot = sh[1023];
    const int ex  = sh[tid] - v;

    if (tid == 0) atomicExch((int*)&g_btot[bid], tot + 1);

    if (tid < bid) {
        int val;
        do { val = atomicAdd((int*)&g_btot[tid], 0); } while (val == 0);
        s_part[tid] = val - 1;
    }
    __syncthreads();
    if (tid == 0) {
        int off = 0;
        for (int b = 0; b < bid; b++) off += s_part[b];
        s_off = off;
    }
    __syncthreads();
    const int off = s_off;

    if (i < n) {
        int rp = off + ex;
        g_rowptr[i] = rp;
        g_wptr[i]   = rp;
        g_dinv[i]   = rsqrtf((float)v + 1.0f);  // +1 self loop
        g_cnt[i]    = 0;                        // reset for next launch
    }
    if (bid == nb - 1 && tid == 1023) g_rowptr[n] = off + tot;  // == e

    __syncthreads();
    if (tid == 0) {
        int d = atomicAdd(&g_bdone, 1);
        if (d == nb - 1) {
            for (int b = 0; b < nb; b++) g_btot[b] = 0;
            g_bdone = 0;
        }
    }
}

__global__ void k_fill(const int* __restrict__ src, const int* __restrict__ dst, int e) {
    int i = blockIdx.x * blockDim.x + threadIdx.x;
    if (i < e) {
        int s = src[i];
        int d = dst[i];
        int idx = atomicAdd(&g_wptr[d], 1);
        g_esrc[idx] = s;
    }
}

// ---------------- tf32 tensor-core GEMM, pipelined + paired fragments ------
// Out[n,M] = (In[n,K] @ W[K,M]) * dinv[row]
//
// k/k+4 fragment pairs stored adjacent as uint2 -> one LDS.64 per fragment
// pair, conflict-free (row stride 20 uint2). The NEXT K-chunk's global loads
// are prefetched into registers before the MMA mainloop of the current chunk,
// so LDG latency overlaps compute instead of stalling the staging phase.
//
// Warp tile: 32 rows x (NG*8) cols.
//   M=128: 4x2 warp grid, BM=128, NG=8
//   M= 64: 4x2 warp grid, BM=128, NG=4
//   M= 16: 8x1 warp grid, BM=256, NG=2
template <int K, int M>
__global__ __launch_bounds__(256)
void k_gemm_tc(const float* __restrict__ In, const float* __restrict__ W,
               float* __restrict__ Out, int n) {
    constexpr int WC = (M >= 64) ? 2 : 1;       // warp col groups
    constexpr int NG = M / (8 * WC);            // 8-col groups per warp
    constexpr int WR = 8 / WC;                  // warp row groups
    constexpr int BM = WR * 32;                 // rows per block
    constexpr int KC = 32;                      // K chunk
    constexpr int LD = 20;                      // uint2 per row (16 + 4 pad)
    constexpr int ASTG = (BM * 4) / 256;        // A stage entries per thread
    constexpr int BCNT = M * 4;                 // total B stage entries
    constexpr int BSTG = (BCNT + 255) / 256;    // B stage entries per thread

    __shared__ uint2 Ap[BM][LD];
    __shared__ uint2 Bp[M][LD];

    const int tid  = threadIdx.x;
    const int warp = tid >> 5, lane = tid & 31;
    const int gid  = lane >> 2;                 // 0..7
    const int tig  = lane & 3;                  // 0..3
    const int row0 = blockIdx.x * BM;
    const int wr   = (WC == 2) ? (warp >> 1) : warp;   // row group
    const int wc   = (WC == 2) ? (warp & 1) : 0;       // col group
    const int rbase = wr * 32;
    const int cbase = wc * NG * 8;

    float4 apre[ASTG][2];
    float  bpre[BSTG][8];

    // ---- prefetch one K-chunk into registers ----
    auto load_chunk = [&](int kk) {
#pragma unroll
        for (int s = 0; s < ASTG; s++) {
            int idx = tid + s * 256;
            int r = idx >> 2, k8 = idx & 3;
            int gr = row0 + r;
            if (gr < n) {
                const float* p = In + (size_t)gr * K + kk + k8 * 8;
                apre[s][0] = *(const float4*)p;
                apre[s][1] = *(const float4*)(p + 4);
            } else {
                apre[s][0] = make_float4(0.f, 0.f, 0.f, 0.f);
                apre[s][1] = apre[s][0];
            }
        }
#pragma unroll
        for (int s = 0; s < BSTG; s++) {
            int idx = tid + s * 256;
            if (idx < BCNT) {
                int c = idx % M, k8 = idx / M;
                const float* p = W + (size_t)(kk + k8 * 8) * M + c;
#pragma unroll
                for (int t = 0; t < 8; t++) bpre[s][t] = p[(size_t)t * M];
            }
        }
    };

    // ---- convert + store the prefetched chunk to smem ----
    auto store_chunk = [&]() {
#pragma unroll
        for (int s = 0; s < ASTG; s++) {
            int idx = tid + s * 256;
            int r = idx >> 2, k8 = idx & 3;
            uint2* q = &Ap[r][k8 * 4];
            q[0] = make_uint2(f2tf32(apre[s][0].x), f2tf32(apre[s][1].x));
            q[1] = make_uint2(f2tf32(apre[s][0].y), f2tf32(apre[s][1].y));
            q[2] = make_uint2(f2tf32(apre[s][0].z), f2tf32(apre[s][1].z));
            q[3] = make_uint2(f2tf32(apre[s][0].w), f2tf32(apre[s][1].w));
        }
#pragma unroll
        for (int s = 0; s < BSTG; s++) {
            int idx = tid + s * 256;
            if (idx < BCNT) {
                int c = idx % M, k8 = idx / M;
                uint2* q = &Bp[c][k8 * 4];
#pragma unroll
                for (int t = 0; t < 4; t++)
                    q[t] = make_uint2(f2tf32(bpre[s][t]), f2tf32(bpre[s][t + 4]));
            }
        }
    };

    float acc[2][NG][4];
#pragma unroll
    for (int rt = 0; rt < 2; rt++)
#pragma unroll
        for (int g = 0; g < NG; g++)
#pragma unroll
            for (int t = 0; t < 4; t++) acc[rt][g][t] = 0.f;

    load_chunk(0);

    for (int kk = 0; kk < K; kk += KC) {
        store_chunk();
        __syncthreads();
        if (kk + KC < K) load_chunk(kk + KC);   // overlaps the MMA loop below

#pragma unroll
        for (int k8 = 0; k8 < KC / 8; k8++) {
            const int kq = k8 * 4 + tig;
            uint2 a00 = Ap[rbase + gid     ][kq];
            uint2 a01 = Ap[rbase + gid + 8 ][kq];
            uint2 a10 = Ap[rbase + 16 + gid    ][kq];
            uint2 a11 = Ap[rbase + 16 + gid + 8][kq];
            uint2 b[NG];
#pragma unroll
            for (int g = 0; g < NG; g++) b[g] = Bp[cbase + g * 8 + gid][kq];
#pragma unroll
            for (int g = 0; g < NG; g++) {
                mma_tf32(acc[0][g], a00.x, a01.x, a00.y, a01.y, b[g].x, b[g].y);
                mma_tf32(acc[1][g], a10.x, a11.x, a10.y, a11.y, b[g].x, b[g].y);
            }
        }
        __syncthreads();
    }

    // ---- epilogue: scale by dinv[row], float2 stores ----
#pragma unroll
    for (int rt = 0; rt < 2; rt++) {
        const int ra = row0 + rbase + rt * 16 + gid;
        const int rb = ra + 8;
        const float sa = (ra < n) ? g_dinv[ra] : 0.f;
        const float sb = (rb < n) ? g_dinv[rb] : 0.f;
#pragma unroll
        for (int g = 0; g < NG; g++) {
            int col = cbase + g * 8 + tig * 2;
            if (ra < n)
                *(float2*)(Out + (size_t)ra * M + col) =
                    make_float2(acc[rt][g][0] * sa, acc[rt][g][1] * sa);
            if (rb < n)
                *(float2*)(Out + (size_t)rb * M + col) =
                    make_float2(acc[rt][g][2] * sb, acc[rt][g][3] * sb);
        }
    }
}

// ---------------- Aggregation (gather-based segment sum) -------------------
// H is pre-scaled: H'[i] = h[i]*dinv[i].
//   out[d] = dinv[d] * ( sum_{e: dst=d} H'[src_e] + H'[d] ) + b
template <int M, bool RELU>
__global__ __launch_bounds__(256)
void agg_kernel(const float* __restrict__ H, const float* __restrict__ bias,
                float* __restrict__ Out, int n) {
    constexpr int NPW = (M >= 32) ? 1 : (32 / M);
    constexpr int CT  = (M >= 128) ? 4 : (M >= 64) ? 2 : 1;

    int gwarp = (blockIdx.x * blockDim.x + threadIdx.x) >> 5;
    int lane  = threadIdx.x & 31;

    int d, c0;
    if constexpr (NPW == 1) {
        d  = gwarp;
        c0 = lane * CT;
    } else {
        d  = gwarp * NPW + lane / M;
        c0 = lane % M;
    }
    if (d >= n) return;

    const float dd = g_dinv[d];

    float acc[CT];
    {
        const float* hd = H + (size_t)d * M + c0;  // self loop
        if constexpr (CT == 4) {
            float4 hv = *(const float4*)hd;
            acc[0] = hv.x; acc[1] = hv.y; acc[2] = hv.z; acc[3] = hv.w;
        } else if constexpr (CT == 2) {
            float2 hv = *(const float2*)hd;
            acc[0] = hv.x; acc[1] = hv.y;
        } else {
            acc[0] = hd[0];
        }
    }

    const int jb = g_rowptr[d], je = g_rowptr[d + 1];
    int j = jb;

    // 8-way unrolled gather: 8 independent row loads in flight per warp.
    for (; j + 8 <= je; j += 8) {
        int s[8];
#pragma unroll
        for (int u = 0; u < 8; u++) s[u] = g_esrc[j + u];
        if constexpr (CT == 4) {
            float4 v[8];
#pragma unroll
            for (int u = 0; u < 8; u++)
                v[u] = *(const float4*)(H + (size_t)s[u] * M + c0);
#pragma unroll
            for (int u = 0; u < 8; u++) {
                acc[0] += v[u].x; acc[1] += v[u].y;
                acc[2] += v[u].z; acc[3] += v[u].w;
            }
        } else if constexpr (CT == 2) {
            float2 v[8];
#pragma unroll
            for (int u = 0; u < 8; u++)
                v[u] = *(const float2*)(H + (size_t)s[u] * M + c0);
#pragma unroll
            for (int u = 0; u < 8; u++) { acc[0] += v[u].x; acc[1] += v[u].y; }
        } else {
            float v[8];
#pragma unroll
            for (int u = 0; u < 8; u++) v[u] = H[(size_t)s[u] * M + c0];
#pragma unroll
            for (int u = 0; u < 8; u++) acc[0] += v[u];
        }
    }
    for (; j + 4 <= je; j += 4) {
        int s0 = g_esrc[j + 0], s1 = g_esrc[j + 1];
        int s2 = g_esrc[j + 2], s3 = g_esrc[j + 3];
        const float* h0 = H + (size_t)s0 * M + c0;
        const float* h1 = H + (size_t)s1 * M + c0;
        const float* h2 = H + (size_t)s2 * M + c0;
        const float* h3 = H + (size_t)s3 * M + c0;
        if constexpr (CT == 4) {
            float4 v0 = *(const float4*)h0;
            float4 v1 = *(const float4*)h1;
            float4 v2 = *(const float4*)h2;
            float4 v3 = *(const float4*)h3;
            acc[0] += (v0.x + v1.x) + (v2.x + v3.x);
            acc[1] += (v0.y + v1.y) + (v2.y + v3.y);
            acc[2] += (v0.z + v1.z) + (v2.z + v3.z);
            acc[3] += (v0.w + v1.w) + (v2.w + v3.w);
        } else if constexpr (CT == 2) {
            float2 v0 = *(const float2*)h0;
            float2 v1 = *(const float2*)h1;
            float2 v2 = *(const float2*)h2;
            float2 v3 = *(const float2*)h3;
            acc[0] += (v0.x + v1.x) + (v2.x + v3.x);
            acc[1] += (v0.y + v1.y) + (v2.y + v3.y);
        } else {
            float v0 = h0[0], v1 = h1[0], v2 = h2[0], v3 = h3[0];
            acc[0] += (v0 + v1) + (v2 + v3);
        }
    }
    for (; j < je; j++) {
        int s = g_esrc[j];
        const float* hs = H + (size_t)s * M + c0;
        if constexpr (CT == 4) {
            float4 v = *(const float4*)hs;
            acc[0] += v.x; acc[1] += v.y; acc[2] += v.z; acc[3] += v.w;
        } else if constexpr (CT == 2) {
            float2 v = *(const float2*)hs;
            acc[0] += v.x; acc[1] += v.y;
        } else {
            acc[0] += hs[0];
        }
    }

#pragma unroll
    for (int t = 0; t < CT; t++) {
        float r = acc[t] * dd + bias[c0 + t];
        acc[t] = RELU ? fmaxf(r, 0.f) : r;
    }

    float* od = Out + (size_t)d * M + c0;
    if constexpr (CT == 4) {
        *(float4*)od = make_float4(acc[0], acc[1], acc[2], acc[3]);
    } else if constexpr (CT == 2) {
        *(float2*)od = make_float2(acc[0], acc[1]);
    } else {
        od[0] = acc[0];
    }
}

// ---------------- launcher -------------------------------------------------
extern "C" void kernel_launch(void* const* d_in, const int* in_sizes, int n_in,
                              void* d_out, int out_size) {
    const float* x  = (const float*)d_in[0];
    const int*   ei = (const int*)d_in[1];   // [2, E] int32
    const float* W1 = (const float*)d_in[2];
    const float* b1 = (const float*)d_in[3];
    const float* W2 = (const float*)d_in[4];
    const float* b2 = (const float*)d_in[5];
    const float* W3 = (const float*)d_in[6];
    const float* b3 = (const float*)d_in[7];

    const int n = in_sizes[0] / 128;
    const int e = in_sizes[1] / 2;
    const int* src = ei;
    const int* dst = ei + e;

    void *pH = nullptr, *pA = nullptr;
    cudaGetSymbolAddress(&pH, g_H);
    cudaGetSymbolAddress(&pA, g_A);
    float* H = (float*)pH;
    float* A = (float*)pA;
    float* out = (float*)d_out;

    const int ge = (e + 255) / 256;
    const int nb = (n + 1023) / 1024;    // 49 <= 64

    // CSR build (dinv ready before GEMM1 so all GEMMs prescale)
    k_count<<<ge, 256>>>(dst, e);
    k_scan_fused<<<nb, 1024>>>(n, nb);
    k_fill<<<ge, 256>>>(src, dst, e);

    // Layer 1: 128 -> 128, ReLU
    k_gemm_tc<128, 128><<<(n + 127) / 128, 256>>>(x, W1, H, n);
    agg_kernel<128, true><<<(n + 7) / 8, 256>>>(H, b1, A, n);

    // Layer 2: 128 -> 64, ReLU
    k_gemm_tc<128, 64><<<(n + 127) / 128, 256>>>(A, W2, H, n);
    agg_kernel<64, true><<<(n + 7) / 8, 256>>>(H, b2, A, n);

    // Layer 3: 64 -> 16
    k_gemm_tc<64, 16><<<(n + 255) / 256, 256>>>(A, W3, H, n);
    {
        const int NPW = 2;  // 16-wide rows, 2 nodes per warp
        int warps  = (n + NPW - 1) / NPW;
        int blocks = (warps * 32 + 255) / 256;
        agg_kernel<16, false><<<blocks, 256>>>(H, b3, out, n);
    }
}

// round 11
// speedup vs baseline: 1.7643x; 1.0114x over previous
#include <cuda_runtime.h>
#include <cuda_bf16.h>
#include <cstdint>

// Problem constants (fixed by dataset; runtime values read from in_sizes).
#define NMAX 50000
#define EMAX 600000

// ---------------- scratch (device globals; no allocation allowed) ----------
// All mutable state is rebuilt every launch; counters/flags are returned to
// zero at the end of each launch -> deterministic across graph replays.
__device__ int   g_cnt[NMAX];
__device__ int   g_rowptr[NMAX + 1];
__device__ int   g_wptr[NMAX];
__device__ int   g_esrc[EMAX];
__device__ float g_dinv[NMAX];
__device__ float g_H[(size_t)NMAX * 128];
__device__ float g_A[(size_t)NMAX * 128];
__device__ volatile int g_btot[64];   // scan block totals (+1 = published)
__device__ int   g_bdone;             // scan completion counter

// ---------------- helpers --------------------------------------------------
__device__ __forceinline__ uint32_t f2tf32(float f) {
    uint32_t u;
    asm("cvt.rna.tf32.f32 %0, %1;" : "=r"(u) : "f"(f));
    return u;
}

__device__ __forceinline__ void mma_tf32(float c[4],
                                         uint32_t a0, uint32_t a1,
                                         uint32_t a2, uint32_t a3,
                                         uint32_t b0, uint32_t b1) {
    asm volatile(
        "mma.sync.aligned.m16n8k8.row.col.f32.tf32.tf32.f32 "
        "{%0,%1,%2,%3}, {%4,%5,%6,%7}, {%8,%9}, {%0,%1,%2,%3};"
        : "+f"(c[0]), "+f"(c[1]), "+f"(c[2]), "+f"(c[3])
        : "r"(a0), "r"(a1), "r"(a2), "r"(a3), "r"(b0), "r"(b1));
}

// ---------------- CSR build ------------------------------------------------
// int4-vectorized edge counting: 4 edges per thread.
__global__ void k_count(const int* __restrict__ dst, int e) {
    int i = blockIdx.x * blockDim.x + threadIdx.x;
    int base = i * 4;
    if (base + 3 < e) {
        int4 d = *(const int4*)(dst + base);
        atomicAdd(&g_cnt[d.x], 1);
        atomicAdd(&g_cnt[d.y], 1);
        atomicAdd(&g_cnt[d.z], 1);
        atomicAdd(&g_cnt[d.w], 1);
    } else {
        for (int k = base; k < e; k++) atomicAdd(&g_cnt[dst[k]], 1);
    }
}

// Single-kernel scan (warp-shuffle + publish/poll; all 49 blocks co-resident).
// Produces rowptr/wptr/dinv; re-zeroes cnt and its own coordination state.
__global__ __launch_bounds__(1024)
void k_scan_fused(int n, int nb) {
    __shared__ int warpsum[32];
    __shared__ int s_part[64];
    __shared__ int s_off;

    const int bid = blockIdx.x, tid = threadIdx.x;
    const int lane = tid & 31, wid = tid >> 5;
    const int i = bid * 1024 + tid;
    int v = (i < n) ? g_cnt[i] : 0;

    // warp inclusive scan
    int x = v;
#pragma unroll
    for (int o = 1; o < 32; o <<= 1) {
        int t = __shfl_up_sync(0xffffffffu, x, o);
        if (lane >= o) x += t;
    }
    if (lane == 31) warpsum[wid] = x;
    __syncthreads();
    if (wid == 0) {
        int wx = warpsum[lane];
#pragma unroll
        for (int o = 1; o < 32; o <<= 1) {
            int t = __shfl_up_sync(0xffffffffu, wx, o);
            if (lane >= o) wx += t;
        }
        warpsum[lane] = wx;  // inclusive over warp totals
    }
    __syncthreads();
    const int basew = (wid == 0) ? 0 : warpsum[wid - 1];
    const int ex  = basew + x - v;   // block-exclusive prefix
    const int tot = warpsum[31];

    // Publish this block's total (+1 marks ready)
    if (tid == 0) atomicExch((int*)&g_btot[bid], tot + 1);

    // Poll all predecessors in parallel (<= 48, all blocks resident)
    if (tid < bid) {
        int val;
        do { val = atomicAdd((int*)&g_btot[tid], 0); } while (val == 0);
        s_part[tid] = val - 1;
    }
    __syncthreads();
    if (tid == 0) {
        int off = 0;
        for (int b = 0; b < bid; b++) off += s_part[b];
        s_off = off;
    }
    __syncthreads();
    const int off = s_off;

    if (i < n) {
        int rp = off + ex;
        g_rowptr[i] = rp;
        g_wptr[i]   = rp;
        g_dinv[i]   = rsqrtf((float)v + 1.0f);  // +1 self loop
        g_cnt[i]    = 0;                        // reset for next launch
    }
    if (bid == nb - 1 && tid == 1023) g_rowptr[n] = off + tot;  // == e

    __syncthreads();
    if (tid == 0) {
        int d = atomicAdd(&g_bdone, 1);
        if (d == nb - 1) {
            for (int b = 0; b < nb; b++) g_btot[b] = 0;
            g_bdone = 0;
        }
    }
}

// ---------------- tf32 tensor-core GEMM, double-buffered + pipelined -------
// Out[n,M] = (In[n,K] @ W[K,M]) * dinv[row]
//
// k/k+4 fragment pairs stored adjacent as uint2 -> one LDS.64 per fragment
// pair, conflict-free (row stride 20 uint2). The NEXT K-chunk's global loads
// are prefetched into registers during the MMA loop, and its smem stores go
// into the OTHER buffer -> ONE __syncthreads() per chunk, STS overlaps MMA.
template <int K, int M>
struct GemmCfg {
    static constexpr int WC = (M >= 64) ? 2 : 1;
    static constexpr int NG = M / (8 * WC);
    static constexpr int WR = 8 / WC;
    static constexpr int BM = WR * 32;
    static constexpr int KC = 32;
    static constexpr int LD = 20;
    static constexpr int NC = K / KC;
    static constexpr int BUFSZ = (BM + M) * LD;              // uint2 per buffer
    static constexpr int SMEM  = 2 * BUFSZ * (int)sizeof(uint2);
};

template <int K, int M>
__device__ __forceinline__ void gemm_tile(const float* __restrict__ In,
                                          const float* __restrict__ W,
                                          float* __restrict__ Out,
                                          int n, int bid) {
    using C = GemmCfg<K, M>;
    constexpr int NG = C::NG, BM = C::BM, KC = C::KC, LD = C::LD, NC = C::NC;
    constexpr int ASTG = (BM * 4) / 256;
    constexpr int BCNT = M * 4;
    constexpr int BSTG = (BCNT + 255) / 256;

    extern __shared__ uint2 dyn[];

    const int tid  = threadIdx.x;
    const int warp = tid >> 5, lane = tid & 31;
    const int gid  = lane >> 2;
    const int tig  = lane & 3;
    const int row0 = bid * BM;
    const int wr   = (C::WC == 2) ? (warp >> 1) : warp;
    const int wc   = (C::WC == 2) ? (warp & 1) : 0;
    const int rbase = wr * 32;
    const int cbase = wc * NG * 8;

    float4 apre[ASTG][2];
    float  bpre[BSTG][8];

    auto load_chunk = [&](int kk) {
#pragma unroll
        for (int s = 0; s < ASTG; s++) {
            int idx = tid + s * 256;
            int r = idx >> 2, k8 = idx & 3;
            int gr = row0 + r;
            if (gr < n) {
                const float* p = In + (size_t)gr * K + kk + k8 * 8;
                apre[s][0] = *(const float4*)p;
                apre[s][1] = *(const float4*)(p + 4);
            } else {
                apre[s][0] = make_float4(0.f, 0.f, 0.f, 0.f);
                apre[s][1] = apre[s][0];
            }
        }
#pragma unroll
        for (int s = 0; s < BSTG; s++) {
            int idx = tid + s * 256;
            if (idx < BCNT) {
                int c = idx % M, k8 = idx / M;
                const float* p = W + (size_t)(kk + k8 * 8) * M + c;
#pragma unroll
                for (int t = 0; t < 8; t++) bpre[s][t] = p[(size_t)t * M];
            }
        }
    };

    auto store_chunk = [&](int buf) {
        uint2* Ap = dyn + buf * C::BUFSZ;       // [BM][LD]
        uint2* Bp = Ap + BM * LD;               // [M][LD]
#pragma unroll
        for (int s = 0; s < ASTG; s++) {
            int idx = tid + s * 256;
            int r = idx >> 2, k8 = idx & 3;
            uint2* q = &Ap[r * LD + k8 * 4];
            q[0] = make_uint2(f2tf32(apre[s][0].x), f2tf32(apre[s][1].x));
            q[1] = make_uint2(f2tf32(apre[s][0].y), f2tf32(apre[s][1].y));
            q[2] = make_uint2(f2tf32(apre[s][0].z), f2tf32(apre[s][1].z));
            q[3] = make_uint2(f2tf32(apre[s][0].w), f2tf32(apre[s][1].w));
        }
#pragma unroll
        for (int s = 0; s < BSTG; s++) {
            int idx = tid + s * 256;
            if (idx < BCNT) {
                int c = idx % M, k8 = idx / M;
                uint2* q = &Bp[c * LD + k8 * 4];
#pragma unroll
                for (int t = 0; t < 4; t++)
                    q[t] = make_uint2(f2tf32(bpre[s][t]), f2tf32(bpre[s][t + 4]));
            }
        }
    };

    float acc[2][NG][4];
#pragma unroll
    for (int rt = 0; rt < 2; rt++)
#pragma unroll
        for (int g = 0; g < NG; g++)
#pragma unroll
            for (int t = 0; t < 4; t++) acc[rt][g][t] = 0.f;

    load_chunk(0);
    store_chunk(0);
    __syncthreads();

    for (int c = 0; c < NC; c++) {
        if (c + 1 < NC) load_chunk((c + 1) * KC);   // LDG overlaps MMA below

        const uint2* Ap = dyn + (c & 1) * C::BUFSZ;
        const uint2* Bp = Ap + BM * LD;
#pragma unroll
        for (int k8 = 0; k8 < KC / 8; k8++) {
            const int kq = k8 * 4 + tig;
            uint2 a00 = Ap[(rbase + gid     ) * LD + kq];
            uint2 a01 = Ap[(rbase + gid + 8 ) * LD + kq];
            uint2 a10 = Ap[(rbase + 16 + gid    ) * LD + kq];
            uint2 a11 = Ap[(rbase + 16 + gid + 8) * LD + kq];
            uint2 b[NG];
#pragma unroll
            for (int g = 0; g < NG; g++)
                b[g] = Bp[(cbase + g * 8 + gid) * LD + kq];
#pragma unroll
            for (int g = 0; g < NG; g++) {
                mma_tf32(acc[0][g], a00.x, a01.x, a00.y, a01.y, b[g].x, b[g].y);
                mma_tf32(acc[1][g], a10.x, a11.x, a10.y, a11.y, b[g].x, b[g].y);
            }
        }

        if (c + 1 < NC) store_chunk((c + 1) & 1);   // other buffer: no WAR
        __syncthreads();                            // one barrier per chunk
    }

    // ---- epilogue: scale by dinv[row], float2 stores ----
#pragma unroll
    for (int rt = 0; rt < 2; rt++) {
        const int ra = row0 + rbase + rt * 16 + gid;
        const int rb = ra + 8;
        const float sa = (ra < n) ? g_dinv[ra] : 0.f;
        const float sb = (rb < n) ? g_dinv[rb] : 0.f;
#pragma unroll
        for (int g = 0; g < NG; g++) {
            int col = cbase + g * 8 + tig * 2;
            if (ra < n)
                *(float2*)(Out + (size_t)ra * M + col) =
                    make_float2(acc[rt][g][0] * sa, acc[rt][g][1] * sa);
            if (rb < n)
                *(float2*)(Out + (size_t)rb * M + col) =
                    make_float2(acc[rt][g][2] * sb, acc[rt][g][3] * sb);
        }
    }
}

template <int K, int M>
__global__ __launch_bounds__(256)
void k_gemm_tc(const float* __restrict__ In, const float* __restrict__ W,
               float* __restrict__ Out, int n) {
    gemm_tile<K, M>(In, W, Out, n, blockIdx.x);
}

// GEMM1 with CSR-fill fused in trailing grid-striding blocks. Fill hides in
// the GEMM's idle issue slots (GEMM is latency-bound at ~37% issue).
__global__ __launch_bounds__(256)
void k_gemm1_fill(const float* __restrict__ x, const float* __restrict__ W1,
                  float* __restrict__ H, int n,
                  const int* __restrict__ src, const int* __restrict__ dst,
                  int e, int gemm_blocks) {
    if ((int)blockIdx.x < gemm_blocks) {
        gemm_tile<128, 128>(x, W1, H, n, blockIdx.x);
    } else {
        int nfb = gridDim.x - gemm_blocks;
        int fb  = blockIdx.x - gemm_blocks;
        for (int i = fb * 256 + threadIdx.x; i < e; i += nfb * 256) {
            int s = src[i];
            int d = dst[i];
            int idx = atomicAdd(&g_wptr[d], 1);
            g_esrc[idx] = s;
        }
    }
}

// ---------------- Aggregation (gather-based segment sum) -------------------
// H is pre-scaled: H'[i] = h[i]*dinv[i].
//   out[d] = dinv[d] * ( sum_{e: dst=d} H'[src_e] + H'[d] ) + b
template <int M, bool RELU>
__global__ __launch_bounds__(256)
void agg_kernel(const float* __restrict__ H, const float* __restrict__ bias,
                float* __restrict__ Out, int n) {
    constexpr int NPW = (M >= 32) ? 1 : (32 / M);
    constexpr int CT  = (M >= 128) ? 4 : (M >= 64) ? 2 : 1;

    int gwarp = (blockIdx.x * blockDim.x + threadIdx.x) >> 5;
    int lane  = threadIdx.x & 31;

    int d, c0;
    if constexpr (NPW == 1) {
        d  = gwarp;
        c0 = lane * CT;
    } else {
        d  = gwarp * NPW + lane / M;
        c0 = lane % M;
    }
    if (d >= n) return;

    const float dd = g_dinv[d];

    float acc[CT];
    const float* hd = H + (size_t)d * M + c0;  // self loop
    if constexpr (CT == 4) {
        float4 hv = *(const float4*)hd;
        acc[0] = hv.x; acc[1] = hv.y; acc[2] = hv.z; acc[3] = hv.w;
    } else if constexpr (CT == 2) {
        float2 hv = *(const float2*)hd;
        acc[0] = hv.x; acc[1] = hv.y;
    } else {
        acc[0] = hd[0];
    }

    auto add1 = [&](int s) {
        const float* hs = H + (size_t)s * M + c0;
        if constexpr (CT == 4) {
            float4 v = *(const float4*)hs;
            acc[0] += v.x; acc[1] += v.y; acc[2] += v.z; acc[3] += v.w;
        } else if constexpr (CT == 2) {
            float2 v = *(const float2*)hs;
            acc[0] += v.x; acc[1] += v.y;
        } else {
            acc[0] += hs[0];
        }
    };

    const int jb = g_rowptr[d], je = g_rowptr[d + 1];
    int j = jb;

    // peel to int4 alignment
    while (j < je && (j & 3)) add1(g_esrc[j++]);

    // 8-edge blocks: 2 x LDG.128 broadcast for indices, 8 gathers in flight
    for (; j + 8 <= je; j += 8) {
        int4 sa = *(const int4*)&g_esrc[j];
        int4 sb = *(const int4*)&g_esrc[j + 4];
        int s[8] = {sa.x, sa.y, sa.z, sa.w, sb.x, sb.y, sb.z, sb.w};
        if constexpr (CT == 4) {
            float4 v[8];
#pragma unroll
            for (int u = 0; u < 8; u++)
                v[u] = *(const float4*)(H + (size_t)s[u] * M + c0);
#pragma unroll
            for (int u = 0; u < 8; u++) {
                acc[0] += v[u].x; acc[1] += v[u].y;
                acc[2] += v[u].z; acc[3] += v[u].w;
            }
        } else if constexpr (CT == 2) {
            float2 v[8];
#pragma unroll
            for (int u = 0; u < 8; u++)
                v[u] = *(const float2*)(H + (size_t)s[u] * M + c0);
#pragma unroll
            for (int u = 0; u < 8; u++) { acc[0] += v[u].x; acc[1] += v[u].y; }
        } else {
            float v[8];
#pragma unroll
            for (int u = 0; u < 8; u++) v[u] = H[(size_t)s[u] * M + c0];
#pragma unroll
            for (int u = 0; u < 8; u++) acc[0] += v[u];
        }
    }
    for (; j + 4 <= je; j += 4) {
        int4 sa = *(const int4*)&g_esrc[j];
        int s[4] = {sa.x, sa.y, sa.z, sa.w};
        if constexpr (CT == 4) {
            float4 v[4];
#pragma unroll
            for (int u = 0; u < 4; u++)
                v[u] = *(const float4*)(H + (size_t)s[u] * M + c0);
#pragma unroll
            for (int u = 0; u < 4; u++) {
                acc[0] += v[u].x; acc[1] += v[u].y;
                acc[2] += v[u].z; acc[3] += v[u].w;
            }
        } else if constexpr (CT == 2) {
            float2 v[4];
#pragma unroll
            for (int u = 0; u < 4; u++)
                v[u] = *(const float2*)(H + (size_t)s[u] * M + c0);
#pragma unroll
            for (int u = 0; u < 4; u++) { acc[0] += v[u].x; acc[1] += v[u].y; }
        } else {
            float v[4];
#pragma unroll
            for (int u = 0; u < 4; u++) v[u] = H[(size_t)s[u] * M + c0];
#pragma unroll
            for (int u = 0; u < 4; u++) acc[0] += v[u];
        }
    }
    while (j < je) add1(g_esrc[j++]);

#pragma unroll
    for (int t = 0; t < CT; t++) {
        float r = acc[t] * dd + bias[c0 + t];
        acc[t] = RELU ? fmaxf(r, 0.f) : r;
    }

    float* od = Out + (size_t)d * M + c0;
    if constexpr (CT == 4) {
        *(float4*)od = make_float4(acc[0], acc[1], acc[2], acc[3]);
    } else if constexpr (CT == 2) {
        *(float2*)od = make_float2(acc[0], acc[1]);
    } else {
        od[0] = acc[0];
    }
}

// ---------------- launcher -------------------------------------------------
extern "C" void kernel_launch(void* const* d_in, const int* in_sizes, int n_in,
                              void* d_out, int out_size) {
    const float* x  = (const float*)d_in[0];
    const int*   ei = (const int*)d_in[1];   // [2, E] int32
    const float* W1 = (const float*)d_in[2];
    const float* b1 = (const float*)d_in[3];
    const float* W2 = (const float*)d_in[4];
    const float* b2 = (const float*)d_in[5];
    const float* W3 = (const float*)d_in[6];
    const float* b3 = (const float*)d_in[7];

    const int n = in_sizes[0] / 128;
    const int e = in_sizes[1] / 2;
    const int* src = ei;
    const int* dst = ei + e;

    void *pH = nullptr, *pA = nullptr;
    cudaGetSymbolAddress(&pH, g_H);
    cudaGetSymbolAddress(&pA, g_A);
    float* H = (float*)pH;
    float* A = (float*)pA;
    float* out = (float*)d_out;

    const int nb  = (n + 1023) / 1024;   // 49 <= 64
    const int gb1 = (n + 127) / 128;     // GEMM1 blocks

    constexpr int SM1 = GemmCfg<128, 128>::SMEM;  // 81920
    constexpr int SM2 = GemmCfg<128, 64>::SMEM;   // 61440
    constexpr int SM3 = GemmCfg<64, 16>::SMEM;    // 87040

    cudaFuncSetAttribute(k_gemm1_fill,
                         cudaFuncAttributeMaxDynamicSharedMemorySize, SM1);
    cudaFuncSetAttribute(k_gemm_tc<128, 64>,
                         cudaFuncAttributeMaxDynamicSharedMemorySize, SM2);
    cudaFuncSetAttribute(k_gemm_tc<64, 16>,
                         cudaFuncAttributeMaxDynamicSharedMemorySize, SM3);

    // CSR build part 1: count + scan (dinv/wptr ready for GEMM1+fill)
    k_count<<<(e / 4 + 255) / 256, 256>>>(dst, e);
    k_scan_fused<<<nb, 1024>>>(n, nb);

    // Layer 1 GEMM (prescaled) with CSR fill fused in trailing blocks
    k_gemm1_fill<<<gb1 + 148, 256, SM1>>>(x, W1, H, n, src, dst, e, gb1);
    agg_kernel<128, true><<<(n + 7) / 8, 256>>>(H, b1, A, n);

    // Layer 2: 128 -> 64, ReLU
    k_gemm_tc<128, 64><<<(n + 127) / 128, 256, SM2>>>(A, W2, H, n);
    agg_kernel<64, true><<<(n + 7) / 8, 256>>>(H, b2, A, n);

    // Layer 3: 64 -> 16
    k_gemm_tc<64, 16><<<(n + 255) / 256, 256, SM3>>>(A, W3, H, n);
    {
        const int NPW = 2;  // 16-wide rows, 2 nodes per warp
        int warps  = (n + NPW - 1) / NPW;
        int blocks = (warps * 32 + 255) / 256;
        agg_kernel<16, false><<<blocks, 256>>>(H, b3, out, n);
    }
}

// round 12
// speedup vs baseline: 1.8475x; 1.0472x over previous
#include <cuda_runtime.h>
#include <cuda_fp16.h>
#include <cuda_bf16.h>
#include <cstdint>

// Problem constants (fixed by dataset; runtime values read from in_sizes).
#define NMAX 50000
#define EMAX 600000

// ---------------- scratch (device globals; no allocation allowed) ----------
// All mutable state is rebuilt every launch; counters/flags are returned to
// zero at the end of each launch -> deterministic across graph replays.
__device__ int   g_cnt[NMAX];
__device__ int   g_rowptr[NMAX + 1];
__device__ int   g_wptr[NMAX];
__device__ int   g_esrc[EMAX];
__device__ float g_dinv[NMAX];
__device__ float g_H[(size_t)NMAX * 128];   // fp32 view (layer 3)
__device__ float g_A[(size_t)NMAX * 128];   // fp32 activations
__device__ volatile int g_btot[64];   // scan block totals (+1 = published)
__device__ int   g_bdone;             // scan completion counter

// ---------------- helpers --------------------------------------------------
__device__ __forceinline__ uint32_t f2tf32(float f) {
    uint32_t u;
    asm("cvt.rna.tf32.f32 %0, %1;" : "=r"(u) : "f"(f));
    return u;
}

__device__ __forceinline__ void mma_tf32(float c[4],
                                         uint32_t a0, uint32_t a1,
                                         uint32_t a2, uint32_t a3,
                                         uint32_t b0, uint32_t b1) {
    asm volatile(
        "mma.sync.aligned.m16n8k8.row.col.f32.tf32.tf32.f32 "
        "{%0,%1,%2,%3}, {%4,%5,%6,%7}, {%8,%9}, {%0,%1,%2,%3};"
        : "+f"(c[0]), "+f"(c[1]), "+f"(c[2]), "+f"(c[3])
        : "r"(a0), "r"(a1), "r"(a2), "r"(a3), "r"(b0), "r"(b1));
}

// ---------------- CSR build ------------------------------------------------
__global__ void k_count(const int* __restrict__ dst, int e) {
    int i = blockIdx.x * blockDim.x + threadIdx.x;
    int base = i * 4;
    if (base + 3 < e) {
        int4 d = *(const int4*)(dst + base);
        atomicAdd(&g_cnt[d.x], 1);
        atomicAdd(&g_cnt[d.y], 1);
        atomicAdd(&g_cnt[d.z], 1);
        atomicAdd(&g_cnt[d.w], 1);
    } else {
        for (int k = base; k < e; k++) atomicAdd(&g_cnt[dst[k]], 1);
    }
}

// Single-kernel scan (warp-shuffle + publish/poll; all 49 blocks co-resident).
__global__ __launch_bounds__(1024)
void k_scan_fused(int n, int nb) {
    __shared__ int warpsum[32];
    __shared__ int s_part[64];
    __shared__ int s_off;

    const int bid = blockIdx.x, tid = threadIdx.x;
    const int lane = tid & 31, wid = tid >> 5;
    const int i = bid * 1024 + tid;
    int v = (i < n) ? g_cnt[i] : 0;

    int x = v;
#pragma unroll
    for (int o = 1; o < 32; o <<= 1) {
        int t = __shfl_up_sync(0xffffffffu, x, o);
        if (lane >= o) x += t;
    }
    if (lane == 31) warpsum[wid] = x;
    __syncthreads();
    if (wid == 0) {
        int wx = warpsum[lane];
#pragma unroll
        for (int o = 1; o < 32; o <<= 1) {
            int t = __shfl_up_sync(0xffffffffu, wx, o);
            if (lane >= o) wx += t;
        }
        warpsum[lane] = wx;
    }
    __syncthreads();
    const int basew = (wid == 0) ? 0 : warpsum[wid - 1];
    const int ex  = basew + x - v;
    const int tot = warpsum[31];

    if (tid == 0) atomicExch((int*)&g_btot[bid], tot + 1);

    if (tid < bid) {
        int val;
        do { val = atomicAdd((int*)&g_btot[tid], 0); } while (val == 0);
        s_part[tid] = val - 1;
    }
    __syncthreads();
    if (tid == 0) {
        int off = 0;
        for (int b = 0; b < bid; b++) off += s_part[b];
        s_off = off;
    }
    __syncthreads();
    const int off = s_off;

    if (i < n) {
        int rp = off + ex;
        g_rowptr[i] = rp;
        g_wptr[i]   = rp;
        g_dinv[i]   = rsqrtf((float)v + 1.0f);  // +1 self loop
        g_cnt[i]    = 0;                        // reset for next launch
    }
    if (bid == nb - 1 && tid == 1023) g_rowptr[n] = off + tot;  // == e

    __syncthreads();
    if (tid == 0) {
        int d = atomicAdd(&g_bdone, 1);
        if (d == nb - 1) {
            for (int b = 0; b < nb; b++) g_btot[b] = 0;
            g_bdone = 0;
        }
    }
}

// ---------------- tf32 tensor-core GEMM, double-buffered + pipelined -------
// Out[n,M] = (In[n,K] @ W[K,M]) * dinv[row];  Out fp16 (HOUT) or fp32.
template <int K, int M>
struct GemmCfg {
    static constexpr int WC = (M >= 64) ? 2 : 1;
    static constexpr int NG = M / (8 * WC);
    static constexpr int WR = 8 / WC;
    static constexpr int BM = WR * 32;
    static constexpr int KC = 32;
    static constexpr int LD = 20;
    static constexpr int NC = K / KC;
    static constexpr int BUFSZ = (BM + M) * LD;              // uint2 per buffer
    static constexpr int SMEM  = 2 * BUFSZ * (int)sizeof(uint2);
};

template <int K, int M, bool HOUT>
__device__ __forceinline__ void gemm_tile(const float* __restrict__ In,
                                          const float* __restrict__ W,
                                          void* __restrict__ Outv,
                                          int n, int bid) {
    using C = GemmCfg<K, M>;
    constexpr int NG = C::NG, BM = C::BM, KC = C::KC, LD = C::LD, NC = C::NC;
    constexpr int ASTG = (BM * 4) / 256;
    constexpr int BCNT = M * 4;
    constexpr int BSTG = (BCNT + 255) / 256;

    extern __shared__ uint2 dyn[];

    const int tid  = threadIdx.x;
    const int warp = tid >> 5, lane = tid & 31;
    const int gid  = lane >> 2;
    const int tig  = lane & 3;
    const int row0 = bid * BM;
    const int wr   = (C::WC == 2) ? (warp >> 1) : warp;
    const int wc   = (C::WC == 2) ? (warp & 1) : 0;
    const int rbase = wr * 32;
    const int cbase = wc * NG * 8;

    float4 apre[ASTG][2];
    float  bpre[BSTG][8];

    auto load_chunk = [&](int kk) {
#pragma unroll
        for (int s = 0; s < ASTG; s++) {
            int idx = tid + s * 256;
            int r = idx >> 2, k8 = idx & 3;
            int gr = row0 + r;
            if (gr < n) {
                const float* p = In + (size_t)gr * K + kk + k8 * 8;
                apre[s][0] = *(const float4*)p;
                apre[s][1] = *(const float4*)(p + 4);
            } else {
                apre[s][0] = make_float4(0.f, 0.f, 0.f, 0.f);
                apre[s][1] = apre[s][0];
            }
        }
#pragma unroll
        for (int s = 0; s < BSTG; s++) {
            int idx = tid + s * 256;
            if (idx < BCNT) {
                int c = idx % M, k8 = idx / M;
                const float* p = W + (size_t)(kk + k8 * 8) * M + c;
#pragma unroll
                for (int t = 0; t < 8; t++) bpre[s][t] = p[(size_t)t * M];
            }
        }
    };

    auto store_chunk = [&](int buf) {
        uint2* Ap = dyn + buf * C::BUFSZ;       // [BM][LD]
        uint2* Bp = Ap + BM * LD;               // [M][LD]
#pragma unroll
        for (int s = 0; s < ASTG; s++) {
            int idx = tid + s * 256;
            int r = idx >> 2, k8 = idx & 3;
            uint2* q = &Ap[r * LD + k8 * 4];
            q[0] = make_uint2(f2tf32(apre[s][0].x), f2tf32(apre[s][1].x));
            q[1] = make_uint2(f2tf32(apre[s][0].y), f2tf32(apre[s][1].y));
            q[2] = make_uint2(f2tf32(apre[s][0].z), f2tf32(apre[s][1].z));
            q[3] = make_uint2(f2tf32(apre[s][0].w), f2tf32(apre[s][1].w));
        }
#pragma unroll
        for (int s = 0; s < BSTG; s++) {
            int idx = tid + s * 256;
            if (idx < BCNT) {
                int c = idx % M, k8 = idx / M;
                uint2* q = &Bp[c * LD + k8 * 4];
#pragma unroll
                for (int t = 0; t < 4; t++)
                    q[t] = make_uint2(f2tf32(bpre[s][t]), f2tf32(bpre[s][t + 4]));
            }
        }
    };

    float acc[2][NG][4];
#pragma unroll
    for (int rt = 0; rt < 2; rt++)
#pragma unroll
        for (int g = 0; g < NG; g++)
#pragma unroll
            for (int t = 0; t < 4; t++) acc[rt][g][t] = 0.f;

    load_chunk(0);
    store_chunk(0);
    __syncthreads();

    for (int c = 0; c < NC; c++) {
        if (c + 1 < NC) load_chunk((c + 1) * KC);   // LDG overlaps MMA below

        const uint2* Ap = dyn + (c & 1) * C::BUFSZ;
        const uint2* Bp = Ap + BM * LD;
#pragma unroll
        for (int k8 = 0; k8 < KC / 8; k8++) {
            const int kq = k8 * 4 + tig;
            uint2 a00 = Ap[(rbase + gid     ) * LD + kq];
            uint2 a01 = Ap[(rbase + gid + 8 ) * LD + kq];
            uint2 a10 = Ap[(rbase + 16 + gid    ) * LD + kq];
            uint2 a11 = Ap[(rbase + 16 + gid + 8) * LD + kq];
            uint2 b[NG];
#pragma unroll
            for (int g = 0; g < NG; g++)
                b[g] = Bp[(cbase + g * 8 + gid) * LD + kq];
#pragma unroll
            for (int g = 0; g < NG; g++) {
                mma_tf32(acc[0][g], a00.x, a01.x, a00.y, a01.y, b[g].x, b[g].y);
                mma_tf32(acc[1][g], a10.x, a11.x, a10.y, a11.y, b[g].x, b[g].y);
            }
        }

        if (c + 1 < NC) store_chunk((c + 1) & 1);   // other buffer: no WAR
        __syncthreads();                            // one barrier per chunk
    }

    // ---- epilogue: scale by dinv[row]; fp16 or fp32 stores ----
#pragma unroll
    for (int rt = 0; rt < 2; rt++) {
        const int ra = row0 + rbase + rt * 16 + gid;
        const int rb = ra + 8;
        const float sa = (ra < n) ? g_dinv[ra] : 0.f;
        const float sb = (rb < n) ? g_dinv[rb] : 0.f;
#pragma unroll
        for (int g = 0; g < NG; g++) {
            int col = cbase + g * 8 + tig * 2;
            if constexpr (HOUT) {
                __half* O = (__half*)Outv;
                if (ra < n)
                    *(__half2*)(O + (size_t)ra * M + col) =
                        __floats2half2_rn(acc[rt][g][0] * sa, acc[rt][g][1] * sa);
                if (rb < n)
                    *(__half2*)(O + (size_t)rb * M + col) =
                        __floats2half2_rn(acc[rt][g][2] * sb, acc[rt][g][3] * sb);
            } else {
                float* O = (float*)Outv;
                if (ra < n)
                    *(float2*)(O + (size_t)ra * M + col) =
                        make_float2(acc[rt][g][0] * sa, acc[rt][g][1] * sa);
                if (rb < n)
                    *(float2*)(O + (size_t)rb * M + col) =
                        make_float2(acc[rt][g][2] * sb, acc[rt][g][3] * sb);
            }
        }
    }
}

template <int K, int M, bool HOUT>
__global__ __launch_bounds__(256)
void k_gemm_tc(const float* __restrict__ In, const float* __restrict__ W,
               void* __restrict__ Out, int n) {
    gemm_tile<K, M, HOUT>(In, W, Out, n, blockIdx.x);
}

// GEMM1 (fp16 out) with CSR-fill fused in trailing grid-striding blocks.
__global__ __launch_bounds__(256)
void k_gemm1_fill(const float* __restrict__ x, const float* __restrict__ W1,
                  void* __restrict__ H, int n,
                  const int* __restrict__ src, const int* __restrict__ dst,
                  int e, int gemm_blocks) {
    if ((int)blockIdx.x < gemm_blocks) {
        gemm_tile<128, 128, true>(x, W1, H, n, blockIdx.x);
    } else {
        int nfb = gridDim.x - gemm_blocks;
        int fb  = blockIdx.x - gemm_blocks;
        for (int i = fb * 256 + threadIdx.x; i < e; i += nfb * 256) {
            int s = src[i];
            int d = dst[i];
            int idx = atomicAdd(&g_wptr[d], 1);
            g_esrc[idx] = s;
        }
    }
}

// ---------------- fp16 aggregation (layers 1 & 2) --------------------------
// H is fp16, pre-scaled: H'[i] = h[i]*dinv[i]. Accumulate fp32, write fp32 A.
//   out[d] = dinv[d] * ( sum_{e: dst=d} H'[src_e] + H'[d] ) + b
// One warp per node. M=128: lane loads 4 halves (uint2); M=64: 2 halves (uint).
template <int M, bool RELU>
__global__ __launch_bounds__(256)
void agg_half_kernel(const __half* __restrict__ H,
                     const float* __restrict__ bias,
                     float* __restrict__ Out, int n) {
    constexpr int HU = (M >= 128) ? 2 : 1;   // half2 units per lane
    constexpr int CF = 2 * HU;               // floats per lane

    int d    = (blockIdx.x * blockDim.x + threadIdx.x) >> 5;
    int lane = threadIdx.x & 31;
    if (d >= n) return;

    const int c0 = lane * CF;                // first half index in row
    const float dd = g_dinv[d];

    float acc[CF];

    auto addrow = [&](const __half* row) {
        if constexpr (HU == 2) {
            uint2 u = *(const uint2*)(row + c0);
            float2 f0 = __half22float2(*reinterpret_cast<__half2*>(&u.x));
            float2 f1 = __half22float2(*reinterpret_cast<__half2*>(&u.y));
            acc[0] += f0.x; acc[1] += f0.y; acc[2] += f1.x; acc[3] += f1.y;
        } else {
            uint32_t u = *(const uint32_t*)(row + c0);
            float2 f0 = __half22float2(*reinterpret_cast<__half2*>(&u));
            acc[0] += f0.x; acc[1] += f0.y;
        }
    };

    // self loop
    {
        const __half* row = H + (size_t)d * M;
        if constexpr (HU == 2) {
            uint2 u = *(const uint2*)(row + c0);
            float2 f0 = __half22float2(*reinterpret_cast<__half2*>(&u.x));
            float2 f1 = __half22float2(*reinterpret_cast<__half2*>(&u.y));
            acc[0] = f0.x; acc[1] = f0.y; acc[2] = f1.x; acc[3] = f1.y;
        } else {
            uint32_t u = *(const uint32_t*)(row + c0);
            float2 f0 = __half22float2(*reinterpret_cast<__half2*>(&u));
            acc[0] = f0.x; acc[1] = f0.y;
        }
    }

    const int jb = g_rowptr[d], je = g_rowptr[d + 1];
    int j = jb;

    while (j < je && (j & 3)) addrow(H + (size_t)g_esrc[j++] * M);

    // 8-edge blocks: 2 x LDG.128 broadcast indices, 8 gathers in flight
    for (; j + 8 <= je; j += 8) {
        int4 sa = *(const int4*)&g_esrc[j];
        int4 sb = *(const int4*)&g_esrc[j + 4];
        int s[8] = {sa.x, sa.y, sa.z, sa.w, sb.x, sb.y, sb.z, sb.w};
        if constexpr (HU == 2) {
            uint2 u[8];
#pragma unroll
            for (int q = 0; q < 8; q++)
                u[q] = *(const uint2*)(H + (size_t)s[q] * M + c0);
#pragma unroll
            for (int q = 0; q < 8; q++) {
                float2 f0 = __half22float2(*reinterpret_cast<__half2*>(&u[q].x));
                float2 f1 = __half22float2(*reinterpret_cast<__half2*>(&u[q].y));
                acc[0] += f0.x; acc[1] += f0.y; acc[2] += f1.x; acc[3] += f1.y;
            }
        } else {
            uint32_t u[8];
#pragma unroll
            for (int q = 0; q < 8; q++)
                u[q] = *(const uint32_t*)(H + (size_t)s[q] * M + c0);
#pragma unroll
            for (int q = 0; q < 8; q++) {
                float2 f0 = __half22float2(*reinterpret_cast<__half2*>(&u[q]));
                acc[0] += f0.x; acc[1] += f0.y;
            }
        }
    }
    for (; j + 4 <= je; j += 4) {
        int4 sa = *(const int4*)&g_esrc[j];
        int s[4] = {sa.x, sa.y, sa.z, sa.w};
#pragma unroll
        for (int q = 0; q < 4; q++) addrow(H + (size_t)s[q] * M);
    }
    while (j < je) addrow(H + (size_t)g_esrc[j++] * M);

#pragma unroll
    for (int t = 0; t < CF; t++) {
        float r = acc[t] * dd + bias[c0 + t];
        acc[t] = RELU ? fmaxf(r, 0.f) : r;
    }

    float* od = Out + (size_t)d * M + c0;
    if constexpr (HU == 2) {
        *(float4*)od = make_float4(acc[0], acc[1], acc[2], acc[3]);
    } else {
        *(float2*)od = make_float2(acc[0], acc[1]);
    }
}

// ---------------- fp32 aggregation (layer 3, M=16) -------------------------
template <int M, bool RELU>
__global__ __launch_bounds__(256)
void agg_kernel(const float* __restrict__ H, const float* __restrict__ bias,
                float* __restrict__ Out, int n) {
    constexpr int NPW = 32 / M;   // nodes per warp (M=16 -> 2)

    int gwarp = (blockIdx.x * blockDim.x + threadIdx.x) >> 5;
    int lane  = threadIdx.x & 31;
    int d  = gwarp * NPW + lane / M;
    int c0 = lane % M;
    if (d >= n) return;

    const float dd = g_dinv[d];
    float acc = H[(size_t)d * M + c0];   // self loop

    const int jb = g_rowptr[d], je = g_rowptr[d + 1];
    int j = jb;
    while (j < je && (j & 3)) acc += H[(size_t)g_esrc[j++] * M + c0];
    for (; j + 8 <= je; j += 8) {
        int4 sa = *(const int4*)&g_esrc[j];
        int4 sb = *(const int4*)&g_esrc[j + 4];
        int s[8] = {sa.x, sa.y, sa.z, sa.w, sb.x, sb.y, sb.z, sb.w};
        float v[8];
#pragma unroll
        for (int u = 0; u < 8; u++) v[u] = H[(size_t)s[u] * M + c0];
#pragma unroll
        for (int u = 0; u < 8; u++) acc += v[u];
    }
    for (; j + 4 <= je; j += 4) {
        int4 sa = *(const int4*)&g_esrc[j];
        int s[4] = {sa.x, sa.y, sa.z, sa.w};
        float v[4];
#pragma unroll
        for (int u = 0; u < 4; u++) v[u] = H[(size_t)s[u] * M + c0];
#pragma unroll
        for (int u = 0; u < 4; u++) acc += v[u];
    }
    while (j < je) acc += H[(size_t)g_esrc[j++] * M + c0];

    float r = acc * dd + bias[c0];
    Out[(size_t)d * M + c0] = RELU ? fmaxf(r, 0.f) : r;
}

// ---------------- launcher -------------------------------------------------
extern "C" void kernel_launch(void* const* d_in, const int* in_sizes, int n_in,
                              void* d_out, int out_size) {
    const float* x  = (const float*)d_in[0];
    const int*   ei = (const int*)d_in[1];   // [2, E] int32
    const float* W1 = (const float*)d_in[2];
    const float* b1 = (const float*)d_in[3];
    const float* W2 = (const float*)d_in[4];
    const float* b2 = (const float*)d_in[5];
    const float* W3 = (const float*)d_in[6];
    const float* b3 = (const float*)d_in[7];

    const int n = in_sizes[0] / 128;
    const int e = in_sizes[1] / 2;
    const int* src = ei;
    const int* dst = ei + e;

    void *pH = nullptr, *pA = nullptr;
    cudaGetSymbolAddress(&pH, g_H);
    cudaGetSymbolAddress(&pA, g_A);
    float*  Hf = (float*)pH;        // fp32 view (layer 3)
    __half* Hh = (__half*)pH;       // fp16 view (layers 1-2)
    float*  A  = (float*)pA;
    float* out = (float*)d_out;

    const int nb  = (n + 1023) / 1024;   // 49 <= 64
    const int gb1 = (n + 127) / 128;     // GEMM1 blocks

    constexpr int SM1 = GemmCfg<128, 128>::SMEM;
    constexpr int SM2 = GemmCfg<128, 64>::SMEM;
    constexpr int SM3 = GemmCfg<64, 16>::SMEM;

    cudaFuncSetAttribute(k_gemm1_fill,
                         cudaFuncAttributeMaxDynamicSharedMemorySize, SM1);
    cudaFuncSetAttribute(k_gemm_tc<128, 64, true>,
                         cudaFuncAttributeMaxDynamicSharedMemorySize, SM2);
    cudaFuncSetAttribute(k_gemm_tc<64, 16, false>,
                         cudaFuncAttributeMaxDynamicSharedMemorySize, SM3);

    // CSR build part 1: count + scan (dinv/wptr ready for GEMM1+fill)
    k_count<<<(e / 4 + 255) / 256, 256>>>(dst, e);
    k_scan_fused<<<nb, 1024>>>(n, nb);

    // Layer 1: GEMM (fp16 out, prescaled) + fused CSR fill; fp16 agg, ReLU
    k_gemm1_fill<<<gb1 + 148, 256, SM1>>>(x, W1, Hh, n, src, dst, e, gb1);
    agg_half_kernel<128, true><<<(n + 7) / 8, 256>>>(Hh, b1, A, n);

    // Layer 2: 128 -> 64 (fp16 out), fp16 agg, ReLU
    k_gemm_tc<128, 64, true><<<(n + 127) / 128, 256, SM2>>>(A, W2, Hh, n);
    agg_half_kernel<64, true><<<(n + 7) / 8, 256>>>(Hh, b2, A, n);

    // Layer 3: 64 -> 16, full fp32 (quantization here would hit output directly)
    k_gemm_tc<64, 16, false><<<(n + 255) / 256, 256, SM3>>>(A, W3, Hf, n);
    {
        const int NPW = 2;
        int warps  = (n + NPW - 1) / NPW;
        int blocks = (warps * 32 + 255) / 256;
        agg_kernel<16, false><<<blocks, 256>>>(Hf, b3, out, n);
    }
}